// round 9
// baseline (speedup 1.0000x reference)
#include <cuda_runtime.h>
#include <cuda_bf16.h>
#include <cstdint>

#define FULLM 0xffffffffu
#define DINLINE __device__ __forceinline__

constexpr int NN = 150000, CC = 256, LL = 50000, KTOP = 200;
constexpr int NU = NN - LL;
constexpr int SEGP = 1376;             // 43 chunks of 32 rows
constexpr int NSEGP = 73;              // 73 * 1376 = 100448 >= NU
constexpr int CHKP = 43;
constexpr int NPAD = NSEGP * SEGP;     // padded unlabeled rows (images)
// fused xpt kernel smem: A (h+l 20480) + B double (2*40960) = 102400
constexpr int SMEM_XPT = 102400;
// ptx mma kernel smem: per stage ph(16896)+pl(16896)+xh(8704)+xl(8704)=51200, x2
constexpr int SMEM_PTX = 102400;

// ---------------- scratch (device globals; no allocation allowed) ------------
__device__ int   g_cls[NN];
__device__ float g_rnorm[NN];
__device__ float g_psum[CC * CC];
__device__ float g_protos[CC * CC];
__device__ float g_S[CC * CC];
__device__ float g_colsum[CC];
__device__ int   g_cntall[CC];
__device__ int   g_cntlab[CC];
// protoN as bf16 hi/lo smem-image: [chunk 8][hl 2][class 256][40 shorts (80B pitch)]
__device__ unsigned short g_Bimg[8 * 2 * 256 * 40];
// masked-p bf16 hi/lo images [NU-row][256] (pad rows stay zero)
__device__ __align__(16) unsigned short g_Ph[(size_t)NPAD * CC];
__device__ __align__(16) unsigned short g_Pl[(size_t)NPAD * CC];
// raw-x (unlabeled rows) bf16 hi/lo images [NPAD][256] (pad rows zero)
__device__ __align__(16) unsigned short g_Xbh[(size_t)NPAD * CC];
__device__ __align__(16) unsigned short g_Xbl[(size_t)NPAD * CC];

// ---------------- helpers ----------------------------------------------------
DINLINE float block_reduce_sum(float v) {
    __shared__ float red[8];
    __shared__ float tot;
    for (int o = 16; o; o >>= 1) v += __shfl_xor_sync(FULLM, v, o);
    if ((threadIdx.x & 31) == 0) red[threadIdx.x >> 5] = v;
    __syncthreads();
    if (threadIdx.x < 32) {
        float s = (threadIdx.x < 8) ? red[threadIdx.x] : 0.f;
        for (int o = 4; o; o >>= 1) s += __shfl_xor_sync(FULLM, s, o);
        if (threadIdx.x == 0) tot = s;
    }
    __syncthreads();
    return tot;
}
DINLINE unsigned fkey(float v) {
    unsigned u = __float_as_uint(v);
    return (u & 0x80000000u) ? ~u : (u | 0x80000000u);
}
DINLINE uint32_t smem_u32(const void* p) {
    uint32_t a;
    asm("{ .reg .u64 t; cvta.to.shared.u64 t, %1; cvt.u32.u64 %0, t; }"
        : "=r"(a) : "l"(p));
    return a;
}
DINLINE uint32_t bf2pk(float hi, float lo) {   // hi -> upper 16 bits
    uint32_t u;
    asm("cvt.rn.bf16x2.f32 %0, %1, %2;" : "=r"(u) : "f"(hi), "f"(lo));
    return u;
}
DINLINE void sts_u2(uint32_t addr, uint32_t a, uint32_t b) {
    asm volatile("st.shared.v2.b32 [%0], {%1, %2};" :: "r"(addr), "r"(a), "r"(b));
}
DINLINE void bsplit(float v, unsigned short& h, unsigned short& l) {
    __nv_bfloat16 hb = __float2bfloat16_rn(v);
    unsigned short hs = __bfloat16_as_ushort(hb);
    float hf = __uint_as_float((uint32_t)hs << 16);
    __nv_bfloat16 lb = __float2bfloat16_rn(v - hf);
    h = hs;
    l = __bfloat16_as_ushort(lb);
}
DINLINE void cpasync16(uint32_t dst, const void* src) {
    asm volatile("cp.async.ca.shared.global [%0], [%1], 16;"
                 :: "r"(dst), "l"(src));
}
#define CP_COMMIT() asm volatile("cp.async.commit_group;" ::: "memory")
#define CP_WAIT0()  asm volatile("cp.async.wait_group 0;" ::: "memory")
#define CP_WAIT1()  asm volatile("cp.async.wait_group 1;" ::: "memory")

DINLINE void ldm_x4(uint32_t* r, uint32_t addr) {
    asm volatile("ldmatrix.sync.aligned.m8n8.x4.shared.b16 {%0,%1,%2,%3}, [%4];"
                 : "=r"(r[0]), "=r"(r[1]), "=r"(r[2]), "=r"(r[3]) : "r"(addr));
}
DINLINE void ldm_x2(uint32_t* r, uint32_t addr) {
    asm volatile("ldmatrix.sync.aligned.m8n8.x2.shared.b16 {%0,%1}, [%2];"
                 : "=r"(r[0]), "=r"(r[1]) : "r"(addr));
}
DINLINE void ldmT_x4(uint32_t* r, uint32_t addr) {
    asm volatile("ldmatrix.sync.aligned.m8n8.x4.trans.shared.b16 {%0,%1,%2,%3}, [%4];"
                 : "=r"(r[0]), "=r"(r[1]), "=r"(r[2]), "=r"(r[3]) : "r"(addr));
}
DINLINE void ldmT_x2(uint32_t* r, uint32_t addr) {
    asm volatile("ldmatrix.sync.aligned.m8n8.x2.trans.shared.b16 {%0,%1}, [%2];"
                 : "=r"(r[0]), "=r"(r[1]) : "r"(addr));
}
DINLINE void mma_bf16(float* c, const uint32_t* a, const uint32_t* b) {
    asm volatile(
        "mma.sync.aligned.m16n8k16.row.col.f32.bf16.bf16.f32 "
        "{%0,%1,%2,%3}, {%4,%5,%6,%7}, {%8,%9}, {%0,%1,%2,%3};"
        : "+f"(c[0]), "+f"(c[1]), "+f"(c[2]), "+f"(c[3])
        : "r"(a[0]), "r"(a[1]), "r"(a[2]), "r"(a[3]), "r"(b[0]), "r"(b[1]));
}

// ---------------- kernel 0: zero accumulators --------------------------------
__global__ void zero_k() {
    int i = blockIdx.x * blockDim.x + threadIdx.x;
    if (i < CC * CC) { g_psum[i] = 0.f; g_S[i] = 0.f; }
    if (i < CC) { g_colsum[i] = 0.f; g_cntall[i] = 0; g_cntlab[i] = 0; }
}

// ---------------- kernel 1: class id, rnorm, hist + x image (unlabeled) ------
__global__ void prep_k(const float* __restrict__ x, const float* __restrict__ labels) {
    __shared__ int s_all[CC], s_lab[CC];
    for (int i = threadIdx.x; i < CC; i += blockDim.x) { s_all[i] = 0; s_lab[i] = 0; }
    __syncthreads();
    int warp = threadIdx.x >> 5, lane = threadIdx.x & 31;
    int wpb = blockDim.x >> 5;
    for (int row = blockIdx.x * wpb + warp; row < NN; row += gridDim.x * wpb) {
        const float* lr = labels + (size_t)row * CC;
        int myc = -1;
        #pragma unroll
        for (int j = 0; j < 8; j++) {
            int c = lane + 32 * j;
            if (lr[c] > 0.5f) myc = c;
        }
        int cls = __reduce_max_sync(FULLM, myc);
        const float4* xr = (const float4*)(x + (size_t)row * CC);
        float ss = 0.f;
        float4 v[2];
        #pragma unroll
        for (int j = 0; j < 2; j++) {
            v[j] = xr[lane + 32 * j];
            ss += v[j].x * v[j].x + v[j].y * v[j].y + v[j].z * v[j].z + v[j].w * v[j].w;
        }
        for (int o = 16; o; o >>= 1) ss += __shfl_xor_sync(FULLM, ss, o);
        if (lane == 0) {
            g_cls[row] = cls;
            g_rnorm[row] = rsqrtf(fmaxf(ss, 1e-12f));
            atomicAdd(&s_all[cls], 1);
            if (row < LL) atomicAdd(&s_lab[cls], 1);
        }
        if (row >= LL) {   // bf16 split image for unlabeled rows (0-based)
            size_t ur = (size_t)(row - LL) * CC;
            #pragma unroll
            for (int j = 0; j < 2; j++) {
                int fb = 4 * (lane + 32 * j);
                uint32_t h0 = bf2pk(v[j].y, v[j].x), h1 = bf2pk(v[j].w, v[j].z);
                float f0 = __uint_as_float(h0 << 16);
                float f1 = __uint_as_float(h0 & 0xffff0000u);
                float f2 = __uint_as_float(h1 << 16);
                float f3 = __uint_as_float(h1 & 0xffff0000u);
                uint32_t l0 = bf2pk(v[j].y - f1, v[j].x - f0);
                uint32_t l1 = bf2pk(v[j].w - f3, v[j].z - f2);
                *(uint2*)(g_Xbh + ur + fb) = make_uint2(h0, h1);
                *(uint2*)(g_Xbl + ur + fb) = make_uint2(l0, l1);
            }
        }
    }
    __syncthreads();
    for (int i = threadIdx.x; i < CC; i += blockDim.x) {
        if (s_all[i]) atomicAdd(&g_cntall[i], s_all[i]);
        if (s_lab[i]) atomicAdd(&g_cntlab[i], s_lab[i]);
    }
}

// ---------------- kernel 2: per-class labeled feature sums (atomic) ----------
__global__ void paccum_k(const float* __restrict__ x) {
    int row = blockIdx.x;
    int f = threadIdx.x;
    int cls = g_cls[row];
    atomicAdd(&g_psum[cls * CC + f], x[(size_t)row * CC + f]);
}

// ---------------- write protoN split (bf16 hi/lo) into image -----------------
DINLINE void write_bimg(int c, int f, float v) {
    unsigned short h, l;
    bsplit(v, h, l);
    int ck = f >> 5, kl = f & 31;
    g_Bimg[((ck * 2 + 0) * 256 + c) * 40 + kl] = h;
    g_Bimg[((ck * 2 + 1) * 256 + c) * 40 + kl] = l;
}

// ---------------- kernel: protos + normalized protoN split -------------------
__global__ void pfin_k() {
    int c = blockIdx.x, f = threadIdx.x;
    float v = g_psum[c * CC + f] / (float)g_cntall[c];
    g_protos[c * CC + f] = v;
    float tot = block_reduce_sum(v * v);
    write_bimg(c, f, v * rsqrtf(fmaxf(tot, 1e-12f)));
}

// ---------------- fused bf16x3 mma GEMM, 128 rows x 256 classes --------------
// 512 threads, 16 warps (wm 0..3 x wn 0..3), warp tile 32m x 64n.
// A: fp32 LDG + in-register bf16 split (single smem buffer, h+l).
// B: protoN image, cp.async double-buffered (h+l per buffer).
// TOPK: epilogue does exact per-row top-k -> g_Ph/g_Pl + colsum (prob path).
// else: direct store of rnorm-scaled logits to OUT.
template <bool TOPK>
__global__ void __launch_bounds__(512, 1)
gemm_xpt_k(const float* __restrict__ X, float* __restrict__ OUT,
           int rnoff, int nrows) {
    extern __shared__ char dsm[];
    __shared__ float s_rn[128];
    __shared__ float cs[CC];

    const int tid = threadIdx.x, lane = tid & 31, wid = tid >> 5;
    const int wm = wid >> 2, wn = wid & 3;
    const int n0 = blockIdx.x * 128;

    const uint32_t uA0 = smem_u32(dsm);          // A: h 10240 + l 10240
    const uint32_t uB0 = uA0 + 20480;            // B buf0: h 20480 + l 20480
    const uint32_t uB1 = uA0 + 61440;            // B buf1

    if (tid < 128)
        s_rn[tid] = (n0 + tid < nrows) ? g_rnorm[rnoff + n0 + tid] : 0.f;
    if (TOPK && tid < CC) cs[tid] = 0.f;

    const int a_row = (lane & 7) + 8 * ((lane >> 3) & 1);
    const int a_kb  = 16 * (lane >> 4);
    const int b_row = lane & 7;
    const int b_kb  = 16 * ((lane >> 3) & 1);
    const uint32_t aoff = (uint32_t)((32 * wm + a_row) * 80 + a_kb);
    const uint32_t bofs = (uint32_t)((64 * wn + b_row) * 80 + b_kb);

    float acc[2][8][4];
    #pragma unroll
    for (int i = 0; i < 2; i++)
        #pragma unroll
        for (int j = 0; j < 8; j++)
            #pragma unroll
            for (int q = 0; q < 4; q++) acc[i][j][q] = 0.f;

    // A staging map: 1024 float4 units, 2 per thread
    const int am0 = tid >> 3, af4 = tid & 7;
    const int am1 = (tid + 512) >> 3;
    const uint32_t aAst0 = uA0 + (uint32_t)(am0 * 80 + 8 * af4);
    const uint32_t aAst1 = uA0 + (uint32_t)(am1 * 80 + 8 * af4);
    const bool aok0 = n0 + am0 < nrows, aok1 = n0 + am1 < nrows;
    const float4 z4 = make_float4(0.f, 0.f, 0.f, 0.f);

    auto storeA = [&](float4 g, uint32_t ad) {
        uint32_t h0 = bf2pk(g.y, g.x), h1 = bf2pk(g.w, g.z);
        float f0 = __uint_as_float(h0 << 16);
        float f1 = __uint_as_float(h0 & 0xffff0000u);
        float f2 = __uint_as_float(h1 << 16);
        float f3 = __uint_as_float(h1 & 0xffff0000u);
        uint32_t l0 = bf2pk(g.y - f1, g.x - f0);
        uint32_t l1 = bf2pk(g.w - f3, g.z - f2);
        sts_u2(ad, h0, h1);
        sts_u2(ad + 10240, l0, l1);
    };
    auto stageB = [&](uint32_t ub, int ckn) {
        const char* srcH = (const char*)g_Bimg + (size_t)((ckn * 2 + 0) * 256) * 80;
        const char* srcL = (const char*)g_Bimg + (size_t)((ckn * 2 + 1) * 256) * 80;
        #pragma unroll
        for (int s = 0; s < 5; s++) {
            int j = tid + 512 * s;
            if (j < 1280) cpasync16(ub + 16 * j, srcH + 16 * j);
            else          cpasync16(ub + 20480 + 16 * (j - 1280), srcL + 16 * (j - 1280));
        }
    };

    float4 ga0 = aok0 ? *(const float4*)(X + (size_t)(n0 + am0) * CC + 4 * af4) : z4;
    float4 ga1 = aok1 ? *(const float4*)(X + (size_t)(n0 + am1) * CC + 4 * af4) : z4;
    stageB(uB0, 0); CP_COMMIT();

    for (int ck = 0; ck < 8; ck++) {
        storeA(ga0, aAst0);
        storeA(ga1, aAst1);
        if (ck < 7) {
            int kf = (ck + 1) * 32;
            ga0 = aok0 ? *(const float4*)(X + (size_t)(n0 + am0) * CC + kf + 4 * af4) : z4;
            ga1 = aok1 ? *(const float4*)(X + (size_t)(n0 + am1) * CC + kf + 4 * af4) : z4;
            stageB((ck & 1) ? uB0 : uB1, ck + 1);
            CP_COMMIT();
            CP_WAIT1();
        } else {
            CP_WAIT0();
        }
        __syncthreads();

        uint32_t uBc = (ck & 1) ? uB1 : uB0;
        #pragma unroll
        for (int ks = 0; ks < 2; ks++) {
            uint32_t ah[2][4], al[2][4];
            #pragma unroll
            for (int mf = 0; mf < 2; mf++) {
                ldm_x4(ah[mf], uA0 + aoff + mf * 1280 + ks * 32);
                ldm_x4(al[mf], uA0 + 10240 + aoff + mf * 1280 + ks * 32);
            }
            #pragma unroll
            for (int ng = 0; ng < 2; ng++) {
                uint32_t bh[4][2], bl[4][2];
                #pragma unroll
                for (int nf = 0; nf < 4; nf++) {
                    uint32_t ba = uBc + bofs + (4 * ng + nf) * 640 + ks * 32;
                    ldm_x2(bh[nf], ba);
                    ldm_x2(bl[nf], ba + 20480);
                }
                #pragma unroll
                for (int mf = 0; mf < 2; mf++)
                    #pragma unroll
                    for (int nf = 0; nf < 4; nf++) {
                        float* a = acc[mf][4 * ng + nf];
                        mma_bf16(a, ah[mf], bh[nf]);
                        mma_bf16(a, al[mf], bh[nf]);
                        mma_bf16(a, ah[mf], bl[nf]);
                    }
            }
        }
        __syncthreads();
    }

    if constexpr (!TOPK) {
        // logits epilogue: direct stores
        #pragma unroll
        for (int mf = 0; mf < 2; mf++) {
            #pragma unroll
            for (int half = 0; half < 2; half++) {
                int rl = 32 * wm + 16 * mf + (lane >> 2) + 8 * half;
                int grow = n0 + rl;
                if (grow < nrows) {
                    float rs = s_rn[rl];
                    float* op = OUT + (size_t)grow * CC + 64 * wn + 2 * (lane & 3);
                    #pragma unroll
                    for (int nf = 0; nf < 8; nf++) {
                        float2 v = make_float2(acc[mf][nf][2 * half] * rs,
                                               acc[mf][nf][2 * half + 1] * rs);
                        *(float2*)(op + 8 * nf) = v;
                    }
                }
            }
        }
    } else {
        // prob epilogue: stage 32-row groups, exact top-k, write Ph/Pl + colsum
        float* stg = (float*)dsm;    // 32 x 264 floats = 33792 B (reuses A/B smem)
        for (int g = 0; g < 4; g++) {
            if (wm == g) {
                #pragma unroll
                for (int mf = 0; mf < 2; mf++)
                    #pragma unroll
                    for (int half = 0; half < 2; half++) {
                        int rowloc = 16 * mf + (lane >> 2) + 8 * half;
                        float rs = s_rn[32 * g + rowloc];
                        float* sp = stg + rowloc * 264 + 64 * wn + 2 * (lane & 3);
                        #pragma unroll
                        for (int nf = 0; nf < 8; nf++) {
                            float2 v = make_float2(acc[mf][nf][2 * half] * rs,
                                                   acc[mf][nf][2 * half + 1] * rs);
                            *(float2*)(sp + 8 * nf) = v;
                        }
                    }
            }
            __syncthreads();
            #pragma unroll
            for (int rr = 0; rr < 2; rr++) {
                int rloc = 2 * wid + rr;
                int grow = n0 + 32 * g + rloc;
                if (grow < nrows) {
                    const float* srow = stg + rloc * 264;
                    float v[8]; unsigned key[8];
                    #pragma unroll
                    for (int j = 0; j < 8; j++) {
                        v[j] = srow[lane + 32 * j];
                        key[j] = fkey(v[j]);
                    }
                    unsigned T = 0;
                    for (int b = 31; b >= 0; b--) {
                        unsigned cand = T | (1u << b);
                        int cnt = 0;
                        #pragma unroll
                        for (int j = 0; j < 8; j++) cnt += (key[j] >= cand);
                        cnt = (int)__reduce_add_sync(FULLM, (unsigned)cnt);
                        if (cnt >= KTOP) T = cand;
                    }
                    int gt = 0;
                    #pragma unroll
                    for (int j = 0; j < 8; j++) gt += (key[j] > T);
                    gt = (int)__reduce_add_sync(FULLM, (unsigned)gt);
                    int r = KTOP - gt;
                    int cum = 0;
                    #pragma unroll
                    for (int j = 0; j < 8; j++) {
                        bool eq = (key[j] == T);
                        unsigned bal = __ballot_sync(FULLM, eq);
                        int pre = cum + __popc(bal & ((1u << lane) - 1u));
                        bool keep = (key[j] > T) || (eq && pre < r);
                        cum += __popc(bal);
                        float o = keep ? v[j] : 0.f;
                        unsigned short h, l;
                        bsplit(o, h, l);
                        size_t idx = (size_t)grow * CC + lane + 32 * j;
                        g_Ph[idx] = h;
                        g_Pl[idx] = l;
                        if (o != 0.f) atomicAdd(&cs[lane + 32 * j], o);
                    }
                }
            }
            __syncthreads();
        }
        if (tid < CC) {
            float c = cs[tid];
            if (c != 0.f) atomicAdd(&g_colsum[tid], c);
        }
    }
}

// ---------------- split-K bf16x3 mma GEMM: S[c][f] += sum_r p[r][c]*x[r][f] --
__global__ void __launch_bounds__(512, 1)
gemm_ptx_mma_k() {
    extern __shared__ char dsm[];
    const uint32_t uS0 = smem_u32(dsm);
    const uint32_t uS1 = uS0 + 51200;

    const int tid = threadIdx.x, lane = tid & 31, wid = tid >> 5;
    const int wm = wid >> 2, wn = wid & 3;
    const int f0 = blockIdx.y * 128;
    const int R0 = blockIdx.x * SEGP;

    auto stage = [&](uint32_t ub, int ck) {
        int r0 = R0 + ck * 32;
        #pragma unroll
        for (int s = 0; s < 6; s++) {
            int t = tid + 512 * s;
            if (t < 2048) {
                int img = t >> 10;
                int r = (t >> 5) & 31;
                int piece = t & 31;
                const char* src = (const char*)(img ? g_Pl : g_Ph)
                                  + (size_t)(r0 + r) * 512 + piece * 16;
                cpasync16(ub + img * 16896 + r * 528 + piece * 16, src);
            } else {
                int t2 = t - 2048;
                int img = t2 >> 9;
                int r = (t2 >> 4) & 31;
                int piece = t2 & 15;
                const char* src = (const char*)(img ? g_Xbl : g_Xbh)
                                  + (size_t)(r0 + r) * 512 + f0 * 2 + piece * 16;
                cpasync16(ub + 33792 + img * 8704 + r * 272 + piece * 16, src);
            }
        }
        CP_COMMIT();
    };

    const int krA = (lane & 7) + 8 * ((lane >> 4) & 1);
    const int cmA = 64 * wm + 8 * ((lane >> 3) & 1);
    const int krB = (lane & 7) + 8 * ((lane >> 3) & 1);
    const uint32_t aoff = (uint32_t)(krA * 528 + 2 * cmA);
    const uint32_t boff = (uint32_t)(krB * 272 + 2 * (32 * wn));

    float acc[4][4][4];
    #pragma unroll
    for (int i = 0; i < 4; i++)
        #pragma unroll
        for (int j = 0; j < 4; j++)
            #pragma unroll
            for (int q = 0; q < 4; q++) acc[i][j][q] = 0.f;

    stage(uS0, 0);

    for (int ck = 0; ck < CHKP; ck++) {
        if (ck + 1 < CHKP) {
            stage((ck & 1) ? uS0 : uS1, ck + 1);
            CP_WAIT1();
        } else {
            CP_WAIT0();
        }
        __syncthreads();

        uint32_t uP = (ck & 1) ? uS1 : uS0;
        uint32_t uX = uP + 33792;
        #pragma unroll
        for (int ks = 0; ks < 2; ks++) {
            uint32_t bh[4][2], bl[4][2];
            #pragma unroll
            for (int nf = 0; nf < 4; nf++) {
                uint32_t ba = uX + (uint32_t)(ks * 16 * 272) + boff + 2 * (8 * nf);
                ldmT_x2(bh[nf], ba);
                ldmT_x2(bl[nf], ba + 8704);
            }
            #pragma unroll
            for (int mf = 0; mf < 4; mf++) {
                uint32_t aa = uP + (uint32_t)(ks * 16 * 528) + aoff + 2 * (16 * mf);
                uint32_t ah[4], al[4];
                ldmT_x4(ah, aa);
                ldmT_x4(al, aa + 16896);
                #pragma unroll
                for (int nf = 0; nf < 4; nf++) {
                    mma_bf16(acc[mf][nf], ah, bh[nf]);
                    mma_bf16(acc[mf][nf], al, bh[nf]);
                    mma_bf16(acc[mf][nf], ah, bl[nf]);
                }
            }
        }
        __syncthreads();
    }

    #pragma unroll
    for (int mf = 0; mf < 4; mf++) {
        #pragma unroll
        for (int nf = 0; nf < 4; nf++) {
            #pragma unroll
            for (int half = 0; half < 2; half++) {
                int c = 64 * wm + 16 * mf + (lane >> 2) + 8 * half;
                int f = f0 + 32 * wn + 8 * nf + 2 * (lane & 3);
                atomicAdd(&g_S[c * CC + f + 0], acc[mf][nf][2 * half + 0]);
                atomicAdd(&g_S[c * CC + f + 1], acc[mf][nf][2 * half + 1]);
            }
        }
    }
}

// ---------------- kernel: proto update + renorm + split write ----------------
__global__ void pfin2_k() {
    int c = blockIdx.x, f = threadIdx.x;
    float cp = g_colsum[c];
    float denom = cp + (float)g_cntlab[c];
    float pv = g_protos[c * CC + f];
    float nv = pv + g_S[c * CC + f] / denom - (cp / denom) * pv;
    float tot = block_reduce_sum(nv * nv);
    write_bimg(c, f, nv * rsqrtf(fmaxf(tot, 1e-12f)));
}

// ---------------- launch ------------------------------------------------------
extern "C" void kernel_launch(void* const* d_in, const int* in_sizes, int n_in,
                              void* d_out, int out_size) {
    (void)in_sizes; (void)n_in; (void)out_size;
    const float* x = (const float*)d_in[0];
    const float* labels = (const float*)d_in[1];
    float* out = (float*)d_out;

    cudaFuncSetAttribute(gemm_xpt_k<true>,
                         cudaFuncAttributeMaxDynamicSharedMemorySize, SMEM_XPT);
    cudaFuncSetAttribute(gemm_xpt_k<false>,
                         cudaFuncAttributeMaxDynamicSharedMemorySize, SMEM_XPT);
    cudaFuncSetAttribute(gemm_ptx_mma_k,
                         cudaFuncAttributeMaxDynamicSharedMemorySize, SMEM_PTX);

    zero_k<<<CC, 256>>>();
    prep_k<<<1480, 256>>>(x, labels);
    paccum_k<<<LL, 256>>>(x);
    pfin_k<<<CC, 256>>>();
    gemm_xpt_k<true><<<(NU + 127) / 128, 512, SMEM_XPT>>>(
        x + (size_t)LL * CC, nullptr, LL, NU);
    gemm_ptx_mma_k<<<dim3(NSEGP, 2), 512, SMEM_PTX>>>();
    pfin2_k<<<CC, 256>>>();
    gemm_xpt_k<false><<<(NN + 127) / 128, 512, SMEM_XPT>>>(x, out, 0, NN);
}

// round 11
// speedup vs baseline: 1.3207x; 1.3207x over previous
#include <cuda_runtime.h>
#include <cuda_fp16.h>
#include <cstdint>

#define FULLM 0xffffffffu
#define DINLINE __device__ __forceinline__

constexpr int NN = 150000, CC = 256, LL = 50000, KTOP = 200;
constexpr int NU = NN - LL;
constexpr int SEGP = 1376;             // 43 chunks of 32 rows
constexpr int NSEGP = 73;              // 73 * 1376 = 100448 >= NU
constexpr int CHKP = 43;
constexpr int NPAD = NSEGP * SEGP;     // padded unlabeled rows
constexpr int NIMG = LL + NPAD;        // 150448 image rows (>= NN, pad zero)
// xpt smem: A-hi double (2*10240) + B h+l double (2*20480) = 61440
constexpr int SMEM_MMA = 61440;
// ptx smem per stage: ph 16896 + xh 8704 + xl 8704 = 34304, x2 = 68608
constexpr int SMEM_PTX = 68608;

// ---------------- scratch (device globals; no allocation allowed) ------------
__device__ float g_prob[(size_t)NU * CC];
__device__ int   g_cls[NN];
__device__ float g_rnorm[NN];
__device__ float g_psum[CC * CC];
__device__ float g_protos[CC * CC];
__device__ float g_S[CC * CC];
__device__ float g_colsum[CC];
__device__ int   g_cntall[CC];
__device__ int   g_cntlab[CC];
// protoN as fp16 hi/lo smem-image: [chunk 8][hl 2][class 256][40 shorts (80B pitch)]
__device__ __align__(16) unsigned short g_Bimg[8 * 2 * 256 * 40];
// masked-p fp16 image [NPAD][256] (pad rows stay zero)
__device__ __align__(16) unsigned short g_Ph[(size_t)NPAD * CC];
// raw-x fp16 hi/lo images, GLOBAL row index [NIMG][256] (pad rows zero)
__device__ __align__(16) unsigned short g_Xh[(size_t)NIMG * CC];
__device__ __align__(16) unsigned short g_Xl[(size_t)NIMG * CC];

// ---------------- helpers ----------------------------------------------------
DINLINE float block_reduce_sum(float v) {
    __shared__ float red[8];
    __shared__ float tot;
    for (int o = 16; o; o >>= 1) v += __shfl_xor_sync(FULLM, v, o);
    if ((threadIdx.x & 31) == 0) red[threadIdx.x >> 5] = v;
    __syncthreads();
    if (threadIdx.x < 32) {
        float s = (threadIdx.x < 8) ? red[threadIdx.x] : 0.f;
        for (int o = 4; o; o >>= 1) s += __shfl_xor_sync(FULLM, s, o);
        if (threadIdx.x == 0) tot = s;
    }
    __syncthreads();
    return tot;
}
DINLINE unsigned fkey(float v) {
    unsigned u = __float_as_uint(v);
    return (u & 0x80000000u) ? ~u : (u | 0x80000000u);
}
DINLINE uint32_t smem_u32(const void* p) {
    uint32_t a;
    asm("{ .reg .u64 t; cvta.to.shared.u64 t, %1; cvt.u32.u64 %0, t; }"
        : "=r"(a) : "l"(p));
    return a;
}
// fp16 split: h = fp16(v), l = fp16(v - h)
DINLINE void hsplit(float v, unsigned short& h, unsigned short& l) {
    __half hh = __float2half_rn(v);
    float hf = __half2float(hh);
    __half ll = __float2half_rn(v - hf);
    h = __half_as_ushort(hh);
    l = __half_as_ushort(ll);
}
DINLINE void cpasync16(uint32_t dst, const void* src) {
    asm volatile("cp.async.ca.shared.global [%0], [%1], 16;"
                 :: "r"(dst), "l"(src));
}
#define CP_COMMIT() asm volatile("cp.async.commit_group;" ::: "memory")
#define CP_WAIT0()  asm volatile("cp.async.wait_group 0;" ::: "memory")
#define CP_WAIT1()  asm volatile("cp.async.wait_group 1;" ::: "memory")

DINLINE void ldm_x4(uint32_t* r, uint32_t addr) {
    asm volatile("ldmatrix.sync.aligned.m8n8.x4.shared.b16 {%0,%1,%2,%3}, [%4];"
                 : "=r"(r[0]), "=r"(r[1]), "=r"(r[2]), "=r"(r[3]) : "r"(addr));
}
DINLINE void ldm_x2(uint32_t* r, uint32_t addr) {
    asm volatile("ldmatrix.sync.aligned.m8n8.x2.shared.b16 {%0,%1}, [%2];"
                 : "=r"(r[0]), "=r"(r[1]) : "r"(addr));
}
DINLINE void ldmT_x4(uint32_t* r, uint32_t addr) {
    asm volatile("ldmatrix.sync.aligned.m8n8.x4.trans.shared.b16 {%0,%1,%2,%3}, [%4];"
                 : "=r"(r[0]), "=r"(r[1]), "=r"(r[2]), "=r"(r[3]) : "r"(addr));
}
DINLINE void ldmT_x2(uint32_t* r, uint32_t addr) {
    asm volatile("ldmatrix.sync.aligned.m8n8.x2.trans.shared.b16 {%0,%1}, [%2];"
                 : "=r"(r[0]), "=r"(r[1]) : "r"(addr));
}
DINLINE void mma_f16(float* c, const uint32_t* a, const uint32_t* b) {
    asm volatile(
        "mma.sync.aligned.m16n8k16.row.col.f32.f16.f16.f32 "
        "{%0,%1,%2,%3}, {%4,%5,%6,%7}, {%8,%9}, {%0,%1,%2,%3};"
        : "+f"(c[0]), "+f"(c[1]), "+f"(c[2]), "+f"(c[3])
        : "r"(a[0]), "r"(a[1]), "r"(a[2]), "r"(a[3]), "r"(b[0]), "r"(b[1]));
}

// ---------------- kernel 0: zero accumulators --------------------------------
__global__ void zero_k() {
    int i = blockIdx.x * blockDim.x + threadIdx.x;
    if (i < CC * CC) { g_psum[i] = 0.f; g_S[i] = 0.f; }
    if (i < CC) { g_colsum[i] = 0.f; g_cntall[i] = 0; g_cntlab[i] = 0; }
}

// ---------------- kernel 1: class id, rnorm, hist + x fp16 image (ALL rows) --
__global__ void prep_k(const float* __restrict__ x, const float* __restrict__ labels) {
    __shared__ int s_all[CC], s_lab[CC];
    for (int i = threadIdx.x; i < CC; i += blockDim.x) { s_all[i] = 0; s_lab[i] = 0; }
    __syncthreads();
    int warp = threadIdx.x >> 5, lane = threadIdx.x & 31;
    int wpb = blockDim.x >> 5;
    for (int row = blockIdx.x * wpb + warp; row < NN; row += gridDim.x * wpb) {
        const float* lr = labels + (size_t)row * CC;
        int myc = -1;
        #pragma unroll
        for (int j = 0; j < 8; j++) {
            int c = lane + 32 * j;
            if (lr[c] > 0.5f) myc = c;
        }
        int cls = __reduce_max_sync(FULLM, myc);
        const float4* xr = (const float4*)(x + (size_t)row * CC);
        float ss = 0.f;
        float4 v[2];
        #pragma unroll
        for (int j = 0; j < 2; j++) {
            v[j] = xr[lane + 32 * j];
            ss += v[j].x * v[j].x + v[j].y * v[j].y + v[j].z * v[j].z + v[j].w * v[j].w;
        }
        for (int o = 16; o; o >>= 1) ss += __shfl_xor_sync(FULLM, ss, o);
        if (lane == 0) {
            g_cls[row] = cls;
            g_rnorm[row] = rsqrtf(fmaxf(ss, 1e-12f));
            atomicAdd(&s_all[cls], 1);
            if (row < LL) atomicAdd(&s_lab[cls], 1);
        }
        // write fp16 split image (all rows, global index)
        size_t ur = (size_t)row * CC;
        #pragma unroll
        for (int j = 0; j < 2; j++) {
            int fb = 4 * (lane + 32 * j);
            unsigned short h[4], l[4];
            hsplit(v[j].x, h[0], l[0]);
            hsplit(v[j].y, h[1], l[1]);
            hsplit(v[j].z, h[2], l[2]);
            hsplit(v[j].w, h[3], l[3]);
            *(uint2*)(g_Xh + ur + fb) = *(uint2*)h;
            *(uint2*)(g_Xl + ur + fb) = *(uint2*)l;
        }
    }
    __syncthreads();
    for (int i = threadIdx.x; i < CC; i += blockDim.x) {
        if (s_all[i]) atomicAdd(&g_cntall[i], s_all[i]);
        if (s_lab[i]) atomicAdd(&g_cntlab[i], s_lab[i]);
    }
}

// ---------------- kernel 2: per-class labeled feature sums (atomic) ----------
__global__ void paccum_k(const float* __restrict__ x) {
    int row = blockIdx.x;
    int f = threadIdx.x;
    int cls = g_cls[row];
    atomicAdd(&g_psum[cls * CC + f], x[(size_t)row * CC + f]);
}

// ---------------- write protoN split (fp16 hi/lo) into image -----------------
DINLINE void write_bimg(int c, int f, float v) {
    unsigned short h, l;
    hsplit(v, h, l);
    int ck = f >> 5, kl = f & 31;
    g_Bimg[((ck * 2 + 0) * 256 + c) * 40 + kl] = h;
    g_Bimg[((ck * 2 + 1) * 256 + c) * 40 + kl] = l;
}

// ---------------- kernel: protos + normalized protoN split -------------------
__global__ void pfin_k() {
    int c = blockIdx.x, f = threadIdx.x;
    float v = g_psum[c * CC + f] / (float)g_cntall[c];
    g_protos[c * CC + f] = v;
    float tot = block_reduce_sum(v * v);
    write_bimg(c, f, v * rsqrtf(fmaxf(tot, 1e-12f)));
}

// ---------------- fp16 2-product mma GEMM: OUT[n][c]=rnorm[n]*(X[n].pN[c]) ---
// block 128 rows x 128 classes (grid.y=2), 8 warps, warp tile 64x32, 2 CTA/SM.
// A: x fp16-HI image, cp.async double-buffered. B: protoN h+l image, dbl-buf.
// D = Ah*Bh + Ah*Bl  (x-side error ~2^-12, measured-safe)
__global__ void __launch_bounds__(256, 2)
gemm_mma_k(float* __restrict__ OUT, int imgoff, int nrows) {
    extern __shared__ char dsm[];
    __shared__ float s_rn[128];
    float* __restrict__ O = OUT ? OUT : g_prob;

    const int tid = threadIdx.x, lane = tid & 31, wid = tid >> 5;
    const int wm = wid >> 2, wn = wid & 3;
    const int n0 = blockIdx.x * 128;
    const int c0 = blockIdx.y * 128;

    const uint32_t uA0 = smem_u32(dsm);
    const uint32_t uA1 = uA0 + 10240;
    const uint32_t uB0 = uA0 + 20480;
    const uint32_t uB1 = uA0 + 40960;

    if (tid < 128) {
        int r = n0 + tid;
        s_rn[tid] = (r < nrows) ? g_rnorm[imgoff + r] : 0.f;
    }

    const int a_row = (lane & 7) + 8 * ((lane >> 3) & 1);
    const int a_kb  = 16 * (lane >> 4);
    const int b_row = lane & 7;
    const int b_kb  = 16 * ((lane >> 3) & 1);
    const uint32_t aoff = (uint32_t)((64 * wm + a_row) * 80 + a_kb);
    const uint32_t bofs = (uint32_t)((32 * wn + b_row) * 80 + b_kb);

    float acc[4][4][4];
    #pragma unroll
    for (int i = 0; i < 4; i++)
        #pragma unroll
        for (int j = 0; j < 4; j++)
            #pragma unroll
            for (int q = 0; q < 4; q++) acc[i][j][q] = 0.f;

    auto stageA = [&](uint32_t ub, int ckn) {
        #pragma unroll
        for (int s = 0; s < 2; s++) {
            int t = tid + 256 * s;            // 512 transfers: 128 rows x 4
            int r = t >> 2, pc = t & 3;
            const unsigned short* src = g_Xh
                + (size_t)(imgoff + n0 + r) * CC + ckn * 32 + pc * 8;
            cpasync16(ub + (uint32_t)(r * 80 + pc * 16), src);
        }
    };
    auto stageB = [&](uint32_t ub, int ckn) {
        const char* srcH = (const char*)g_Bimg + (size_t)((ckn * 2 + 0) * 256 + c0) * 80;
        const char* srcL = (const char*)g_Bimg + (size_t)((ckn * 2 + 1) * 256 + c0) * 80;
        #pragma unroll
        for (int s = 0; s < 5; s++) {
            int j = tid + 256 * s;
            if (j < 640) cpasync16(ub + 16 * j, srcH + 16 * j);
            else         cpasync16(ub + 10240 + 16 * (j - 640), srcL + 16 * (j - 640));
        }
    };

    stageA(uA0, 0); stageB(uB0, 0); CP_COMMIT();

    for (int ck = 0; ck < 8; ck++) {
        uint32_t uAc = (ck & 1) ? uA1 : uA0;
        uint32_t uBc = (ck & 1) ? uB1 : uB0;
        if (ck < 7) {
            stageA((ck & 1) ? uA0 : uA1, ck + 1);
            stageB((ck & 1) ? uB0 : uB1, ck + 1);
            CP_COMMIT();
            CP_WAIT1();
        } else {
            CP_WAIT0();
        }
        __syncthreads();

        #pragma unroll
        for (int ks = 0; ks < 2; ks++) {
            uint32_t bh[4][2], bl[4][2];
            #pragma unroll
            for (int nf = 0; nf < 4; nf++) {
                ldm_x2(bh[nf], uBc + bofs + nf * 640 + ks * 32);
                ldm_x2(bl[nf], uBc + 10240 + bofs + nf * 640 + ks * 32);
            }
            #pragma unroll
            for (int mf = 0; mf < 4; mf++) {
                uint32_t ah[4];
                ldm_x4(ah, uAc + aoff + mf * 1280 + ks * 32);
                #pragma unroll
                for (int nf = 0; nf < 4; nf++) {
                    mma_f16(acc[mf][nf], ah, bh[nf]);
                    mma_f16(acc[mf][nf], ah, bl[nf]);
                }
            }
        }
        __syncthreads();
    }

    #pragma unroll
    for (int mf = 0; mf < 4; mf++) {
        #pragma unroll
        for (int half = 0; half < 2; half++) {
            int rl = 64 * wm + 16 * mf + (lane >> 2) + 8 * half;
            int grow = n0 + rl;
            if (grow < nrows) {
                float rs = s_rn[rl];
                float* op = O + (size_t)grow * CC + c0 + 32 * wn + 2 * (lane & 3);
                #pragma unroll
                for (int nf = 0; nf < 4; nf++) {
                    float2 v = make_float2(acc[mf][nf][2 * half] * rs,
                                           acc[mf][nf][2 * half + 1] * rs);
                    *(float2*)(op + 8 * nf) = v;
                }
            }
        }
    }
}

// ---------------- kernel: exact per-row top-k -> fp16 p image ----------------
__global__ void topk_k() {
    __shared__ float cs[CC];
    for (int i = threadIdx.x; i < CC; i += blockDim.x) cs[i] = 0.f;
    __syncthreads();
    int warp = threadIdx.x >> 5, lane = threadIdx.x & 31;
    for (int row = blockIdx.x * 8 + warp; row < NU; row += gridDim.x * 8) {
        const float* pr = g_prob + (size_t)row * CC;
        float v[8]; unsigned key[8];
        #pragma unroll
        for (int j = 0; j < 8; j++) { v[j] = pr[lane + 32 * j]; key[j] = fkey(v[j]); }
        unsigned T = 0;
        for (int b = 31; b >= 0; b--) {
            unsigned cand = T | (1u << b);
            int cnt = 0;
            #pragma unroll
            for (int j = 0; j < 8; j++) cnt += (key[j] >= cand);
            cnt = (int)__reduce_add_sync(FULLM, (unsigned)cnt);
            if (cnt >= KTOP) T = cand;
        }
        int gt = 0;
        #pragma unroll
        for (int j = 0; j < 8; j++) gt += (key[j] > T);
        gt = (int)__reduce_add_sync(FULLM, (unsigned)gt);
        int r = KTOP - gt;
        int cum = 0;
        #pragma unroll
        for (int j = 0; j < 8; j++) {
            bool eq = (key[j] == T);
            unsigned bal = __ballot_sync(FULLM, eq);
            int pre = cum + __popc(bal & ((1u << lane) - 1u));
            bool keep = (key[j] > T) || (eq && pre < r);
            cum += __popc(bal);
            float o = keep ? v[j] : 0.f;
            g_Ph[(size_t)row * CC + lane + 32 * j] =
                __half_as_ushort(__float2half_rn(o));
            if (o != 0.f) atomicAdd(&cs[lane + 32 * j], o);
        }
    }
    __syncthreads();
    float c = cs[threadIdx.x];
    if (c != 0.f) atomicAdd(&g_colsum[threadIdx.x], c);
}

// ---------------- split-K fp16 2-product GEMM: S[c][f]+=sum_r p[r][c]x[r][f] -
// D = Ph*Xh + Ph*Xl  (p-side error ~2^-12). Stage: ph[32][528] xh/xl[32][272].
__global__ void __launch_bounds__(512, 1)
gemm_ptx_mma_k() {
    extern __shared__ char dsm[];
    const uint32_t uS0 = smem_u32(dsm);
    const uint32_t uS1 = uS0 + 34304;

    const int tid = threadIdx.x, lane = tid & 31, wid = tid >> 5;
    const int wm = wid >> 2, wn = wid & 3;
    const int f0 = blockIdx.y * 128;
    const int R0 = blockIdx.x * SEGP;

    auto stage = [&](uint32_t ub, int ck) {
        int r0 = R0 + ck * 32;
        #pragma unroll
        for (int s = 0; s < 4; s++) {        // 2048 transfers, 4/thread
            int t = tid + 512 * s;
            if (t < 1024) {                  // ph: 32 rows x 32 pieces (512B)
                int r = t >> 5, piece = t & 31;
                const char* src = (const char*)g_Ph
                                  + (size_t)(r0 + r) * 512 + piece * 16;
                cpasync16(ub + r * 528 + piece * 16, src);
            } else if (t < 1536) {           // xh: 32 rows x 16 pieces (256B)
                int t2 = t - 1024;
                int r = t2 >> 4, piece = t2 & 15;
                const char* src = (const char*)g_Xh
                                  + (size_t)(LL + r0 + r) * 512 + f0 * 2 + piece * 16;
                cpasync16(ub + 16896 + r * 272 + piece * 16, src);
            } else {                         // xl
                int t2 = t - 1536;
                int r = t2 >> 4, piece = t2 & 15;
                const char* src = (const char*)g_Xl
                                  + (size_t)(LL + r0 + r) * 512 + f0 * 2 + piece * 16;
                cpasync16(ub + 25600 + r * 272 + piece * 16, src);
            }
        }
        CP_COMMIT();
    };

    const int krA = (lane & 7) + 8 * ((lane >> 4) & 1);
    const int cmA = 64 * wm + 8 * ((lane >> 3) & 1);
    const int krB = (lane & 7) + 8 * ((lane >> 3) & 1);
    const uint32_t aoff = (uint32_t)(krA * 528 + 2 * cmA);
    const uint32_t boff = (uint32_t)(krB * 272 + 2 * (32 * wn));

    float acc[4][4][4];
    #pragma unroll
    for (int i = 0; i < 4; i++)
        #pragma unroll
        for (int j = 0; j < 4; j++)
            #pragma unroll
            for (int q = 0; q < 4; q++) acc[i][j][q] = 0.f;

    stage(uS0, 0);

    for (int ck = 0; ck < CHKP; ck++) {
        if (ck + 1 < CHKP) {
            stage((ck & 1) ? uS0 : uS1, ck + 1);
            CP_WAIT1();
        } else {
            CP_WAIT0();
        }
        __syncthreads();

        uint32_t uP = (ck & 1) ? uS1 : uS0;
        uint32_t uXh = uP + 16896;
        uint32_t uXl = uP + 25600;
        #pragma unroll
        for (int ks = 0; ks < 2; ks++) {
            uint32_t bh[4][2], bl[4][2];
            #pragma unroll
            for (int nf = 0; nf < 4; nf++) {
                uint32_t bo = (uint32_t)(ks * 16 * 272) + boff + 2 * (8 * nf);
                ldmT_x2(bh[nf], uXh + bo);
                ldmT_x2(bl[nf], uXl + bo);
            }
            #pragma unroll
            for (int mf = 0; mf < 4; mf++) {
                uint32_t aa = uP + (uint32_t)(ks * 16 * 528) + aoff + 2 * (16 * mf);
                uint32_t ah[4];
                ldmT_x4(ah, aa);
                #pragma unroll
                for (int nf = 0; nf < 4; nf++) {
                    mma_f16(acc[mf][nf], ah, bh[nf]);
                    mma_f16(acc[mf][nf], ah, bl[nf]);
                }
            }
        }
        __syncthreads();
    }

    #pragma unroll
    for (int mf = 0; mf < 4; mf++) {
        #pragma unroll
        for (int nf = 0; nf < 4; nf++) {
            #pragma unroll
            for (int half = 0; half < 2; half++) {
                int c = 64 * wm + 16 * mf + (lane >> 2) + 8 * half;
                int f = f0 + 32 * wn + 8 * nf + 2 * (lane & 3);
                atomicAdd(&g_S[c * CC + f + 0], acc[mf][nf][2 * half + 0]);
                atomicAdd(&g_S[c * CC + f + 1], acc[mf][nf][2 * half + 1]);
            }
        }
    }
}

// ---------------- kernel: proto update + renorm + split write ----------------
__global__ void pfin2_k() {
    int c = blockIdx.x, f = threadIdx.x;
    float cp = g_colsum[c];
    float denom = cp + (float)g_cntlab[c];
    float pv = g_protos[c * CC + f];
    float nv = pv + g_S[c * CC + f] / denom - (cp / denom) * pv;
    float tot = block_reduce_sum(nv * nv);
    write_bimg(c, f, nv * rsqrtf(fmaxf(tot, 1e-12f)));
}

// ---------------- launch ------------------------------------------------------
extern "C" void kernel_launch(void* const* d_in, const int* in_sizes, int n_in,
                              void* d_out, int out_size) {
    (void)in_sizes; (void)n_in; (void)out_size;
    const float* x = (const float*)d_in[0];
    const float* labels = (const float*)d_in[1];
    float* out = (float*)d_out;

    cudaFuncSetAttribute(gemm_mma_k,
                         cudaFuncAttributeMaxDynamicSharedMemorySize, SMEM_MMA);
    cudaFuncSetAttribute(gemm_ptx_mma_k,
                         cudaFuncAttributeMaxDynamicSharedMemorySize, SMEM_PTX);

    zero_k<<<CC, 256>>>();
    prep_k<<<1480, 256>>>(x, labels);
    paccum_k<<<LL, 256>>>(x);
    pfin_k<<<CC, 256>>>();
    gemm_mma_k<<<dim3((NU + 127) / 128, 2), 256, SMEM_MMA>>>(nullptr, LL, NU);
    topk_k<<<1563, 256>>>();
    gemm_ptx_mma_k<<<dim3(NSEGP, 2), 512, SMEM_PTX>>>();
    pfin2_k<<<CC, 256>>>();
    gemm_mma_k<<<dim3((NN + 127) / 128, 2), 256, SMEM_MMA>>>(out, 0, NN);
}

// round 12
// speedup vs baseline: 1.5276x; 1.1567x over previous
#include <cuda_runtime.h>
#include <cuda_fp16.h>
#include <cstdint>

#define FULLM 0xffffffffu
#define DINLINE __device__ __forceinline__

constexpr int NN = 150000, CC = 256, LL = 50000, KTOP = 200;
constexpr int NU = NN - LL;
constexpr int SEGP = 1376;             // 43 chunks of 32 rows
constexpr int NSEGP = 73;              // 73 * 1376 = 100448 >= NU
constexpr int CHKP = 43;
constexpr int NPAD = NSEGP * SEGP;     // padded unlabeled rows
constexpr int NIMG = LL + NPAD;        // 150448 image rows (>= NN, pad zero)
// xpt smem: A-hi double (2*10240) + B h+l double (2*20480) = 61440
constexpr int SMEM_MMA = 61440;
// ptx smem per stage: ph 16896 + xh 8704 + xl 8704 = 34304, x2 = 68608
constexpr int SMEM_PTX = 68608;

// ---------------- scratch (device globals; no allocation allowed) ------------
__device__ float g_prob[(size_t)NU * CC];
__device__ float g_rnorm[NN];
__device__ float g_psum[CC * CC];
__device__ float g_protos[CC * CC];
__device__ float g_S[CC * CC];
__device__ float g_colsum[CC];
__device__ int   g_cntall[CC];
__device__ int   g_cntlab[CC];
// protoN as fp16 hi/lo smem-image: [chunk 8][hl 2][class 256][40 shorts (80B pitch)]
__device__ __align__(16) unsigned short g_Bimg[8 * 2 * 256 * 40];
// masked-p fp16 image [NPAD][256] (pad rows stay zero)
__device__ __align__(16) unsigned short g_Ph[(size_t)NPAD * CC];
// raw-x fp16 hi/lo images, GLOBAL row index [NIMG][256] (pad rows zero)
__device__ __align__(16) unsigned short g_Xh[(size_t)NIMG * CC];
__device__ __align__(16) unsigned short g_Xl[(size_t)NIMG * CC];

// ---------------- helpers ----------------------------------------------------
DINLINE float block_reduce_sum(float v) {
    __shared__ float red[8];
    __shared__ float tot;
    for (int o = 16; o; o >>= 1) v += __shfl_xor_sync(FULLM, v, o);
    if ((threadIdx.x & 31) == 0) red[threadIdx.x >> 5] = v;
    __syncthreads();
    if (threadIdx.x < 32) {
        float s = (threadIdx.x < 8) ? red[threadIdx.x] : 0.f;
        for (int o = 4; o; o >>= 1) s += __shfl_xor_sync(FULLM, s, o);
        if (threadIdx.x == 0) tot = s;
    }
    __syncthreads();
    return tot;
}
DINLINE unsigned fkey(float v) {
    unsigned u = __float_as_uint(v);
    return (u & 0x80000000u) ? ~u : (u | 0x80000000u);
}
DINLINE uint32_t smem_u32(const void* p) {
    uint32_t a;
    asm("{ .reg .u64 t; cvta.to.shared.u64 t, %1; cvt.u32.u64 %0, t; }"
        : "=r"(a) : "l"(p));
    return a;
}
// fp16 split: h = fp16(v), l = fp16(v - h)
DINLINE void hsplit(float v, unsigned short& h, unsigned short& l) {
    __half hh = __float2half_rn(v);
    float hf = __half2float(hh);
    __half ll = __float2half_rn(v - hf);
    h = __half_as_ushort(hh);
    l = __half_as_ushort(ll);
}
DINLINE void cpasync16(uint32_t dst, const void* src) {
    asm volatile("cp.async.ca.shared.global [%0], [%1], 16;"
                 :: "r"(dst), "l"(src));
}
#define CP_COMMIT() asm volatile("cp.async.commit_group;" ::: "memory")
#define CP_WAIT0()  asm volatile("cp.async.wait_group 0;" ::: "memory")
#define CP_WAIT1()  asm volatile("cp.async.wait_group 1;" ::: "memory")

DINLINE void ldm_x4(uint32_t* r, uint32_t addr) {
    asm volatile("ldmatrix.sync.aligned.m8n8.x4.shared.b16 {%0,%1,%2,%3}, [%4];"
                 : "=r"(r[0]), "=r"(r[1]), "=r"(r[2]), "=r"(r[3]) : "r"(addr));
}
DINLINE void ldm_x2(uint32_t* r, uint32_t addr) {
    asm volatile("ldmatrix.sync.aligned.m8n8.x2.shared.b16 {%0,%1}, [%2];"
                 : "=r"(r[0]), "=r"(r[1]) : "r"(addr));
}
DINLINE void ldmT_x4(uint32_t* r, uint32_t addr) {
    asm volatile("ldmatrix.sync.aligned.m8n8.x4.trans.shared.b16 {%0,%1,%2,%3}, [%4];"
                 : "=r"(r[0]), "=r"(r[1]), "=r"(r[2]), "=r"(r[3]) : "r"(addr));
}
DINLINE void ldmT_x2(uint32_t* r, uint32_t addr) {
    asm volatile("ldmatrix.sync.aligned.m8n8.x2.trans.shared.b16 {%0,%1}, [%2];"
                 : "=r"(r[0]), "=r"(r[1]) : "r"(addr));
}
DINLINE void mma_f16(float* c, const uint32_t* a, const uint32_t* b) {
    asm volatile(
        "mma.sync.aligned.m16n8k16.row.col.f32.f16.f16.f32 "
        "{%0,%1,%2,%3}, {%4,%5,%6,%7}, {%8,%9}, {%0,%1,%2,%3};"
        : "+f"(c[0]), "+f"(c[1]), "+f"(c[2]), "+f"(c[3])
        : "r"(a[0]), "r"(a[1]), "r"(a[2]), "r"(a[3]), "r"(b[0]), "r"(b[1]));
}

// ---------------- kernel 0: zero accumulators --------------------------------
__global__ void zero_k() {
    int i = blockIdx.x * blockDim.x + threadIdx.x;
    if (i < CC * CC) { g_psum[i] = 0.f; g_S[i] = 0.f; }
    if (i < CC) { g_colsum[i] = 0.f; g_cntall[i] = 0; g_cntlab[i] = 0; }
}

// ---------------- kernel 1: cls, rnorm, hist, psum atomics, x fp16 image -----
__global__ void prep_k(const float* __restrict__ x, const float* __restrict__ labels) {
    __shared__ int s_all[CC], s_lab[CC];
    for (int i = threadIdx.x; i < CC; i += blockDim.x) { s_all[i] = 0; s_lab[i] = 0; }
    __syncthreads();
    int warp = threadIdx.x >> 5, lane = threadIdx.x & 31;
    int wpb = blockDim.x >> 5;
    for (int row = blockIdx.x * wpb + warp; row < NN; row += gridDim.x * wpb) {
        const float* lr = labels + (size_t)row * CC;
        int myc = -1;
        #pragma unroll
        for (int j = 0; j < 8; j++) {
            int c = lane + 32 * j;
            if (lr[c] > 0.5f) myc = c;
        }
        int cls = __reduce_max_sync(FULLM, myc);
        const float4* xr = (const float4*)(x + (size_t)row * CC);
        float ss = 0.f;
        float4 v[2];
        #pragma unroll
        for (int j = 0; j < 2; j++) {
            v[j] = xr[lane + 32 * j];
            ss += v[j].x * v[j].x + v[j].y * v[j].y + v[j].z * v[j].z + v[j].w * v[j].w;
        }
        for (int o = 16; o; o >>= 1) ss += __shfl_xor_sync(FULLM, ss, o);
        if (lane == 0) {
            g_rnorm[row] = rsqrtf(fmaxf(ss, 1e-12f));
            atomicAdd(&s_all[cls], 1);
            if (row < LL) atomicAdd(&s_lab[cls], 1);
        }
        if (row < LL) {   // fused per-class labeled feature sums
            float* ps = g_psum + cls * CC;
            #pragma unroll
            for (int j = 0; j < 2; j++) {
                int fb = 4 * (lane + 32 * j);
                atomicAdd(ps + fb + 0, v[j].x);
                atomicAdd(ps + fb + 1, v[j].y);
                atomicAdd(ps + fb + 2, v[j].z);
                atomicAdd(ps + fb + 3, v[j].w);
            }
        }
        // write fp16 split image (all rows, global index)
        size_t ur = (size_t)row * CC;
        #pragma unroll
        for (int j = 0; j < 2; j++) {
            int fb = 4 * (lane + 32 * j);
            unsigned short h[4], l[4];
            hsplit(v[j].x, h[0], l[0]);
            hsplit(v[j].y, h[1], l[1]);
            hsplit(v[j].z, h[2], l[2]);
            hsplit(v[j].w, h[3], l[3]);
            *(uint2*)(g_Xh + ur + fb) = *(uint2*)h;
            *(uint2*)(g_Xl + ur + fb) = *(uint2*)l;
        }
    }
    __syncthreads();
    for (int i = threadIdx.x; i < CC; i += blockDim.x) {
        if (s_all[i]) atomicAdd(&g_cntall[i], s_all[i]);
        if (s_lab[i]) atomicAdd(&g_cntlab[i], s_lab[i]);
    }
}

// ---------------- write protoN split (fp16 hi/lo) into image -----------------
DINLINE void write_bimg(int c, int f, float v) {
    unsigned short h, l;
    hsplit(v, h, l);
    int ck = f >> 5, kl = f & 31;
    g_Bimg[((ck * 2 + 0) * 256 + c) * 40 + kl] = h;
    g_Bimg[((ck * 2 + 1) * 256 + c) * 40 + kl] = l;
}

// ---------------- kernel: protos + normalized protoN split -------------------
__global__ void pfin_k() {
    int c = blockIdx.x, f = threadIdx.x;
    float v = g_psum[c * CC + f] / (float)g_cntall[c];
    g_protos[c * CC + f] = v;
    float tot = block_reduce_sum(v * v);
    write_bimg(c, f, v * rsqrtf(fmaxf(tot, 1e-12f)));
}

// ---------------- fp16 2-product mma GEMM: OUT[n][c]=rnorm[n]*(X[n].pN[c]) ---
// block 128 rows x 128 classes (grid.y=2), 8 warps, warp tile 64x32, 2 CTA/SM.
// D = Ah*Bh + Ah*Bl
__global__ void __launch_bounds__(256, 2)
gemm_mma_k(float* __restrict__ OUT, int imgoff, int nrows) {
    extern __shared__ char dsm[];
    __shared__ float s_rn[128];
    float* __restrict__ O = OUT ? OUT : g_prob;

    const int tid = threadIdx.x, lane = tid & 31, wid = tid >> 5;
    const int wm = wid >> 2, wn = wid & 3;
    const int n0 = blockIdx.x * 128;
    const int c0 = blockIdx.y * 128;

    const uint32_t uA0 = smem_u32(dsm);
    const uint32_t uA1 = uA0 + 10240;
    const uint32_t uB0 = uA0 + 20480;
    const uint32_t uB1 = uA0 + 40960;

    if (tid < 128) {
        int r = n0 + tid;
        s_rn[tid] = (r < nrows) ? g_rnorm[imgoff + r] : 0.f;
    }

    const int a_row = (lane & 7) + 8 * ((lane >> 3) & 1);
    const int a_kb  = 16 * (lane >> 4);
    const int b_row = lane & 7;
    const int b_kb  = 16 * ((lane >> 3) & 1);
    const uint32_t aoff = (uint32_t)((64 * wm + a_row) * 80 + a_kb);
    const uint32_t bofs = (uint32_t)((32 * wn + b_row) * 80 + b_kb);

    float acc[4][4][4];
    #pragma unroll
    for (int i = 0; i < 4; i++)
        #pragma unroll
        for (int j = 0; j < 4; j++)
            #pragma unroll
            for (int q = 0; q < 4; q++) acc[i][j][q] = 0.f;

    auto stageA = [&](uint32_t ub, int ckn) {
        #pragma unroll
        for (int s = 0; s < 2; s++) {
            int t = tid + 256 * s;            // 512 transfers: 128 rows x 4
            int r = t >> 2, pc = t & 3;
            const unsigned short* src = g_Xh
                + (size_t)(imgoff + n0 + r) * CC + ckn * 32 + pc * 8;
            cpasync16(ub + (uint32_t)(r * 80 + pc * 16), src);
        }
    };
    auto stageB = [&](uint32_t ub, int ckn) {
        const char* srcH = (const char*)g_Bimg + (size_t)((ckn * 2 + 0) * 256 + c0) * 80;
        const char* srcL = (const char*)g_Bimg + (size_t)((ckn * 2 + 1) * 256 + c0) * 80;
        #pragma unroll
        for (int s = 0; s < 5; s++) {
            int j = tid + 256 * s;
            if (j < 640) cpasync16(ub + 16 * j, srcH + 16 * j);
            else         cpasync16(ub + 10240 + 16 * (j - 640), srcL + 16 * (j - 640));
        }
    };

    stageA(uA0, 0); stageB(uB0, 0); CP_COMMIT();

    for (int ck = 0; ck < 8; ck++) {
        uint32_t uAc = (ck & 1) ? uA1 : uA0;
        uint32_t uBc = (ck & 1) ? uB1 : uB0;
        if (ck < 7) {
            stageA((ck & 1) ? uA0 : uA1, ck + 1);
            stageB((ck & 1) ? uB0 : uB1, ck + 1);
            CP_COMMIT();
            CP_WAIT1();
        } else {
            CP_WAIT0();
        }
        __syncthreads();

        #pragma unroll
        for (int ks = 0; ks < 2; ks++) {
            uint32_t bh[4][2], bl[4][2];
            #pragma unroll
            for (int nf = 0; nf < 4; nf++) {
                ldm_x2(bh[nf], uBc + bofs + nf * 640 + ks * 32);
                ldm_x2(bl[nf], uBc + 10240 + bofs + nf * 640 + ks * 32);
            }
            #pragma unroll
            for (int mf = 0; mf < 4; mf++) {
                uint32_t ah[4];
                ldm_x4(ah, uAc + aoff + mf * 1280 + ks * 32);
                #pragma unroll
                for (int nf = 0; nf < 4; nf++) {
                    mma_f16(acc[mf][nf], ah, bh[nf]);
                    mma_f16(acc[mf][nf], ah, bl[nf]);
                }
            }
        }
        __syncthreads();
    }

    #pragma unroll
    for (int mf = 0; mf < 4; mf++) {
        #pragma unroll
        for (int half = 0; half < 2; half++) {
            int rl = 64 * wm + 16 * mf + (lane >> 2) + 8 * half;
            int grow = n0 + rl;
            if (grow < nrows) {
                float rs = s_rn[rl];
                float* op = O + (size_t)grow * CC + c0 + 32 * wn + 2 * (lane & 3);
                #pragma unroll
                for (int nf = 0; nf < 4; nf++) {
                    float2 v = make_float2(acc[mf][nf][2 * half] * rs,
                                           acc[mf][nf][2 * half + 1] * rs);
                    *(float2*)(op + 8 * nf) = v;
                }
            }
        }
    }
}

// ---------------- kernel: exact per-row top-k (early exit) -> fp16 p image ---
__global__ void topk_k() {
    __shared__ float cs[CC];
    for (int i = threadIdx.x; i < CC; i += blockDim.x) cs[i] = 0.f;
    __syncthreads();
    int warp = threadIdx.x >> 5, lane = threadIdx.x & 31;
    for (int row = blockIdx.x * 8 + warp; row < NU; row += gridDim.x * 8) {
        const float* pr = g_prob + (size_t)row * CC;
        float v[8]; unsigned key[8];
        #pragma unroll
        for (int j = 0; j < 8; j++) { v[j] = pr[lane + 32 * j]; key[j] = fkey(v[j]); }
        unsigned T = 0;
        for (int b = 31; b >= 0; b--) {
            unsigned cand = T | (1u << b);
            int cnt = 0;
            #pragma unroll
            for (int j = 0; j < 8; j++) cnt += (key[j] >= cand);
            cnt = (int)__reduce_add_sync(FULLM, (unsigned)cnt);
            if (cnt >= KTOP) {
                T = cand;
                if (cnt == KTOP) break;   // prefix already selects exactly top-K
            }
        }
        int gt = 0;
        #pragma unroll
        for (int j = 0; j < 8; j++) gt += (key[j] > T);
        gt = (int)__reduce_add_sync(FULLM, (unsigned)gt);
        int r = KTOP - gt;
        int cum = 0;
        #pragma unroll
        for (int j = 0; j < 8; j++) {
            bool eq = (key[j] == T);
            unsigned bal = __ballot_sync(FULLM, eq);
            int pre = cum + __popc(bal & ((1u << lane) - 1u));
            bool keep = (key[j] > T) || (eq && pre < r);
            cum += __popc(bal);
            float o = keep ? v[j] : 0.f;
            g_Ph[(size_t)row * CC + lane + 32 * j] =
                __half_as_ushort(__float2half_rn(o));
            if (o != 0.f) atomicAdd(&cs[lane + 32 * j], o);
        }
    }
    __syncthreads();
    float c = cs[threadIdx.x];
    if (c != 0.f) atomicAdd(&g_colsum[threadIdx.x], c);
}

// ---------------- split-K fp16 2-product GEMM: S[c][f]+=sum_r p[r][c]x[r][f] -
__global__ void __launch_bounds__(512, 1)
gemm_ptx_mma_k() {
    extern __shared__ char dsm[];
    const uint32_t uS0 = smem_u32(dsm);
    const uint32_t uS1 = uS0 + 34304;

    const int tid = threadIdx.x, lane = tid & 31, wid = tid >> 5;
    const int wm = wid >> 2, wn = wid & 3;
    const int f0 = blockIdx.y * 128;
    const int R0 = blockIdx.x * SEGP;

    auto stage = [&](uint32_t ub, int ck) {
        int r0 = R0 + ck * 32;
        #pragma unroll
        for (int s = 0; s < 4; s++) {
            int t = tid + 512 * s;
            if (t < 1024) {
                int r = t >> 5, piece = t & 31;
                const char* src = (const char*)g_Ph
                                  + (size_t)(r0 + r) * 512 + piece * 16;
                cpasync16(ub + r * 528 + piece * 16, src);
            } else if (t < 1536) {
                int t2 = t - 1024;
                int r = t2 >> 4, piece = t2 & 15;
                const char* src = (const char*)g_Xh
                                  + (size_t)(LL + r0 + r) * 512 + f0 * 2 + piece * 16;
                cpasync16(ub + 16896 + r * 272 + piece * 16, src);
            } else {
                int t2 = t - 1536;
                int r = t2 >> 4, piece = t2 & 15;
                const char* src = (const char*)g_Xl
                                  + (size_t)(LL + r0 + r) * 512 + f0 * 2 + piece * 16;
                cpasync16(ub + 25600 + r * 272 + piece * 16, src);
            }
        }
        CP_COMMIT();
    };

    const int krA = (lane & 7) + 8 * ((lane >> 4) & 1);
    const int cmA = 64 * wm + 8 * ((lane >> 3) & 1);
    const int krB = (lane & 7) + 8 * ((lane >> 3) & 1);
    const uint32_t aoff = (uint32_t)(krA * 528 + 2 * cmA);
    const uint32_t boff = (uint32_t)(krB * 272 + 2 * (32 * wn));

    float acc[4][4][4];
    #pragma unroll
    for (int i = 0; i < 4; i++)
        #pragma unroll
        for (int j = 0; j < 4; j++)
            #pragma unroll
            for (int q = 0; q < 4; q++) acc[i][j][q] = 0.f;

    stage(uS0, 0);

    for (int ck = 0; ck < CHKP; ck++) {
        if (ck + 1 < CHKP) {
            stage((ck & 1) ? uS0 : uS1, ck + 1);
            CP_WAIT1();
        } else {
            CP_WAIT0();
        }
        __syncthreads();

        uint32_t uP = (ck & 1) ? uS1 : uS0;
        uint32_t uXh = uP + 16896;
        uint32_t uXl = uP + 25600;
        #pragma unroll
        for (int ks = 0; ks < 2; ks++) {
            uint32_t bh[4][2], bl[4][2];
            #pragma unroll
            for (int nf = 0; nf < 4; nf++) {
                uint32_t bo = (uint32_t)(ks * 16 * 272) + boff + 2 * (8 * nf);
                ldmT_x2(bh[nf], uXh + bo);
                ldmT_x2(bl[nf], uXl + bo);
            }
            #pragma unroll
            for (int mf = 0; mf < 4; mf++) {
                uint32_t aa = uP + (uint32_t)(ks * 16 * 528) + aoff + 2 * (16 * mf);
                uint32_t ah[4];
                ldmT_x4(ah, aa);
                #pragma unroll
                for (int nf = 0; nf < 4; nf++) {
                    mma_f16(acc[mf][nf], ah, bh[nf]);
                    mma_f16(acc[mf][nf], ah, bl[nf]);
                }
            }
        }
        __syncthreads();
    }

    #pragma unroll
    for (int mf = 0; mf < 4; mf++) {
        #pragma unroll
        for (int nf = 0; nf < 4; nf++) {
            #pragma unroll
            for (int half = 0; half < 2; half++) {
                int c = 64 * wm + 16 * mf + (lane >> 2) + 8 * half;
                int f = f0 + 32 * wn + 8 * nf + 2 * (lane & 3);
                atomicAdd(&g_S[c * CC + f + 0], acc[mf][nf][2 * half + 0]);
                atomicAdd(&g_S[c * CC + f + 1], acc[mf][nf][2 * half + 1]);
            }
        }
    }
}

// ---------------- kernel: proto update + renorm + split write ----------------
__global__ void pfin2_k() {
    int c = blockIdx.x, f = threadIdx.x;
    float cp = g_colsum[c];
    float denom = cp + (float)g_cntlab[c];
    float pv = g_protos[c * CC + f];
    float nv = pv + g_S[c * CC + f] / denom - (cp / denom) * pv;
    float tot = block_reduce_sum(nv * nv);
    write_bimg(c, f, nv * rsqrtf(fmaxf(tot, 1e-12f)));
}

// ---------------- launch ------------------------------------------------------
extern "C" void kernel_launch(void* const* d_in, const int* in_sizes, int n_in,
                              void* d_out, int out_size) {
    (void)in_sizes; (void)n_in; (void)out_size;
    const float* x = (const float*)d_in[0];
    const float* labels = (const float*)d_in[1];
    float* out = (float*)d_out;

    cudaFuncSetAttribute(gemm_mma_k,
                         cudaFuncAttributeMaxDynamicSharedMemorySize, SMEM_MMA);
    cudaFuncSetAttribute(gemm_ptx_mma_k,
                         cudaFuncAttributeMaxDynamicSharedMemorySize, SMEM_PTX);

    zero_k<<<CC, 256>>>();                                    // 1
    prep_k<<<1480, 256>>>(x, labels);                         // 2 (+psum fused)
    pfin_k<<<CC, 256>>>();                                    // 3
    gemm_mma_k<<<dim3((NU + 127) / 128, 2), 256, SMEM_MMA>>>( // 4 <- ncu capture
        nullptr, LL, NU);
    topk_k<<<1563, 256>>>();                                  // 5
    gemm_ptx_mma_k<<<dim3(NSEGP, 2), 512, SMEM_PTX>>>();      // 6
    pfin2_k<<<CC, 256>>>();                                   // 7
    gemm_mma_k<<<dim3((NN + 127) / 128, 2), 256, SMEM_MMA>>>(out, 0, NN); // 8
}

// round 13
// speedup vs baseline: 1.5308x; 1.0021x over previous
#include <cuda_runtime.h>
#include <cuda_fp16.h>
#include <cstdint>

#define FULLM 0xffffffffu
#define DINLINE __device__ __forceinline__

constexpr int NN = 150000, CC = 256, LL = 50000, KTOP = 200;
constexpr int NU = NN - LL;
constexpr int SEGP = 1376;             // 43 chunks of 32 rows
constexpr int NSEGP = 73;              // 73 * 1376 = 100448 >= NU
constexpr int CHKP = 43;
constexpr int NPAD = NSEGP * SEGP;     // padded unlabeled rows
constexpr int NIMG = LL + NPAD;        // 150448 image rows (>= NN, pad zero)
// xpt smem: A-hi double (2*10240) + B h+l double (2*20480) = 61440
constexpr int SMEM_MMA = 61440;
// ptx smem per stage: ph 16896 + xh 8704 + xl 8704 = 34304, x2 = 68608
constexpr int SMEM_PTX = 68608;

// ---------------- scratch (device globals; no allocation allowed) ------------
__device__ float g_prob[(size_t)NU * CC];
__device__ float g_rnorm[NN];
__device__ float g_psum[CC * CC];
__device__ float g_protos[CC * CC];
__device__ float g_S[CC * CC];
__device__ float g_colsum[CC];
__device__ int   g_cntall[CC];
__device__ int   g_cntlab[CC];
// protoN as fp16 hi/lo smem-image: [chunk 8][hl 2][class 256][40 shorts (80B pitch)]
__device__ __align__(16) unsigned short g_Bimg[8 * 2 * 256 * 40];
// masked-p fp16 image [NPAD][256] (pad rows stay zero)
__device__ __align__(16) unsigned short g_Ph[(size_t)NPAD * CC];
// raw-x fp16 hi/lo images, GLOBAL row index [NIMG][256] (pad rows zero)
__device__ __align__(16) unsigned short g_Xh[(size_t)NIMG * CC];
__device__ __align__(16) unsigned short g_Xl[(size_t)NIMG * CC];

// ---------------- helpers ----------------------------------------------------
DINLINE float block_reduce_sum(float v) {
    __shared__ float red[8];
    __shared__ float tot;
    for (int o = 16; o; o >>= 1) v += __shfl_xor_sync(FULLM, v, o);
    if ((threadIdx.x & 31) == 0) red[threadIdx.x >> 5] = v;
    __syncthreads();
    if (threadIdx.x < 32) {
        float s = (threadIdx.x < 8) ? red[threadIdx.x] : 0.f;
        for (int o = 4; o; o >>= 1) s += __shfl_xor_sync(FULLM, s, o);
        if (threadIdx.x == 0) tot = s;
    }
    __syncthreads();
    return tot;
}
DINLINE unsigned fkey(float v) {
    unsigned u = __float_as_uint(v);
    return (u & 0x80000000u) ? ~u : (u | 0x80000000u);
}
DINLINE uint32_t smem_u32(const void* p) {
    uint32_t a;
    asm("{ .reg .u64 t; cvta.to.shared.u64 t, %1; cvt.u32.u64 %0, t; }"
        : "=r"(a) : "l"(p));
    return a;
}
// fp16 split: h = fp16(v), l = fp16(v - h)
DINLINE void hsplit(float v, unsigned short& h, unsigned short& l) {
    __half hh = __float2half_rn(v);
    float hf = __half2float(hh);
    __half ll = __float2half_rn(v - hf);
    h = __half_as_ushort(hh);
    l = __half_as_ushort(ll);
}
DINLINE void cpasync16(uint32_t dst, const void* src) {
    asm volatile("cp.async.ca.shared.global [%0], [%1], 16;"
                 :: "r"(dst), "l"(src));
}
#define CP_COMMIT() asm volatile("cp.async.commit_group;" ::: "memory")
#define CP_WAIT0()  asm volatile("cp.async.wait_group 0;" ::: "memory")
#define CP_WAIT1()  asm volatile("cp.async.wait_group 1;" ::: "memory")

DINLINE void ldm_x4(uint32_t* r, uint32_t addr) {
    asm volatile("ldmatrix.sync.aligned.m8n8.x4.shared.b16 {%0,%1,%2,%3}, [%4];"
                 : "=r"(r[0]), "=r"(r[1]), "=r"(r[2]), "=r"(r[3]) : "r"(addr));
}
DINLINE void ldm_x2(uint32_t* r, uint32_t addr) {
    asm volatile("ldmatrix.sync.aligned.m8n8.x2.shared.b16 {%0,%1}, [%2];"
                 : "=r"(r[0]), "=r"(r[1]) : "r"(addr));
}
DINLINE void ldmT_x4(uint32_t* r, uint32_t addr) {
    asm volatile("ldmatrix.sync.aligned.m8n8.x4.trans.shared.b16 {%0,%1,%2,%3}, [%4];"
                 : "=r"(r[0]), "=r"(r[1]), "=r"(r[2]), "=r"(r[3]) : "r"(addr));
}
DINLINE void ldmT_x2(uint32_t* r, uint32_t addr) {
    asm volatile("ldmatrix.sync.aligned.m8n8.x2.trans.shared.b16 {%0,%1}, [%2];"
                 : "=r"(r[0]), "=r"(r[1]) : "r"(addr));
}
DINLINE void mma_f16(float* c, const uint32_t* a, const uint32_t* b) {
    asm volatile(
        "mma.sync.aligned.m16n8k16.row.col.f32.f16.f16.f32 "
        "{%0,%1,%2,%3}, {%4,%5,%6,%7}, {%8,%9}, {%0,%1,%2,%3};"
        : "+f"(c[0]), "+f"(c[1]), "+f"(c[2]), "+f"(c[3])
        : "r"(a[0]), "r"(a[1]), "r"(a[2]), "r"(a[3]), "r"(b[0]), "r"(b[1]));
}

// ---------------- kernel 0: zero accumulators --------------------------------
__global__ void zero_k() {
    int i = blockIdx.x * blockDim.x + threadIdx.x;
    if (i < CC * CC) { g_psum[i] = 0.f; g_S[i] = 0.f; }
    if (i < CC) { g_colsum[i] = 0.f; g_cntall[i] = 0; g_cntlab[i] = 0; }
}

// ---------------- kernel 1: cls, rnorm, hist, psum atomics, x fp16 image -----
__global__ void prep_k(const float* __restrict__ x, const float* __restrict__ labels) {
    __shared__ int s_all[CC], s_lab[CC];
    for (int i = threadIdx.x; i < CC; i += blockDim.x) { s_all[i] = 0; s_lab[i] = 0; }
    __syncthreads();
    int warp = threadIdx.x >> 5, lane = threadIdx.x & 31;
    int wpb = blockDim.x >> 5;
    for (int row = blockIdx.x * wpb + warp; row < NN; row += gridDim.x * wpb) {
        const float4* lr4 = (const float4*)(labels + (size_t)row * CC);
        int myc = -1;
        #pragma unroll
        for (int j = 0; j < 2; j++) {
            float4 lv = lr4[lane + 32 * j];
            int cb = 4 * (lane + 32 * j);
            if (lv.x > 0.5f) myc = cb + 0;
            if (lv.y > 0.5f) myc = cb + 1;
            if (lv.z > 0.5f) myc = cb + 2;
            if (lv.w > 0.5f) myc = cb + 3;
        }
        int cls = __reduce_max_sync(FULLM, myc);
        const float4* xr = (const float4*)(x + (size_t)row * CC);
        float ss = 0.f;
        float4 v[2];
        #pragma unroll
        for (int j = 0; j < 2; j++) {
            v[j] = xr[lane + 32 * j];
            ss += v[j].x * v[j].x + v[j].y * v[j].y + v[j].z * v[j].z + v[j].w * v[j].w;
        }
        for (int o = 16; o; o >>= 1) ss += __shfl_xor_sync(FULLM, ss, o);
        if (lane == 0) {
            g_rnorm[row] = rsqrtf(fmaxf(ss, 1e-12f));
            atomicAdd(&s_all[cls], 1);
            if (row < LL) atomicAdd(&s_lab[cls], 1);
        }
        if (row < LL) {   // fused per-class labeled feature sums
            float* ps = g_psum + cls * CC;
            #pragma unroll
            for (int j = 0; j < 2; j++) {
                int fb = 4 * (lane + 32 * j);
                atomicAdd(ps + fb + 0, v[j].x);
                atomicAdd(ps + fb + 1, v[j].y);
                atomicAdd(ps + fb + 2, v[j].z);
                atomicAdd(ps + fb + 3, v[j].w);
            }
        }
        // write fp16 split image (all rows, global index)
        size_t ur = (size_t)row * CC;
        #pragma unroll
        for (int j = 0; j < 2; j++) {
            int fb = 4 * (lane + 32 * j);
            unsigned short h[4], l[4];
            hsplit(v[j].x, h[0], l[0]);
            hsplit(v[j].y, h[1], l[1]);
            hsplit(v[j].z, h[2], l[2]);
            hsplit(v[j].w, h[3], l[3]);
            *(uint2*)(g_Xh + ur + fb) = *(uint2*)h;
            *(uint2*)(g_Xl + ur + fb) = *(uint2*)l;
        }
    }
    __syncthreads();
    for (int i = threadIdx.x; i < CC; i += blockDim.x) {
        if (s_all[i]) atomicAdd(&g_cntall[i], s_all[i]);
        if (s_lab[i]) atomicAdd(&g_cntlab[i], s_lab[i]);
    }
}

// ---------------- write protoN split (fp16 hi/lo) into image -----------------
DINLINE void write_bimg(int c, int f, float v) {
    unsigned short h, l;
    hsplit(v, h, l);
    int ck = f >> 5, kl = f & 31;
    g_Bimg[((ck * 2 + 0) * 256 + c) * 40 + kl] = h;
    g_Bimg[((ck * 2 + 1) * 256 + c) * 40 + kl] = l;
}

// ---------------- kernel: protos + normalized protoN split -------------------
__global__ void pfin_k() {
    int c = blockIdx.x, f = threadIdx.x;
    float v = g_psum[c * CC + f] / (float)g_cntall[c];
    g_protos[c * CC + f] = v;
    float tot = block_reduce_sum(v * v);
    write_bimg(c, f, v * rsqrtf(fmaxf(tot, 1e-12f)));
}

// ---------------- fp16 2-product mma GEMM: OUT[n][c]=rnorm[n]*(X[n].pN[c]) ---
// block 128 rows x 128 classes (grid.y=2), 8 warps, warp tile 64x32, 2 CTA/SM.
// D = Ah*Bh + Ah*Bl
__global__ void __launch_bounds__(256, 2)
gemm_mma_k(float* __restrict__ OUT, int imgoff, int nrows) {
    extern __shared__ char dsm[];
    __shared__ float s_rn[128];
    float* __restrict__ O = OUT ? OUT : g_prob;

    const int tid = threadIdx.x, lane = tid & 31, wid = tid >> 5;
    const int wm = wid >> 2, wn = wid & 3;
    const int n0 = blockIdx.x * 128;
    const int c0 = blockIdx.y * 128;

    const uint32_t uA0 = smem_u32(dsm);
    const uint32_t uA1 = uA0 + 10240;
    const uint32_t uB0 = uA0 + 20480;
    const uint32_t uB1 = uA0 + 40960;

    if (tid < 128) {
        int r = n0 + tid;
        s_rn[tid] = (r < nrows) ? g_rnorm[imgoff + r] : 0.f;
    }

    const int a_row = (lane & 7) + 8 * ((lane >> 3) & 1);
    const int a_kb  = 16 * (lane >> 4);
    const int b_row = lane & 7;
    const int b_kb  = 16 * ((lane >> 3) & 1);
    const uint32_t aoff = (uint32_t)((64 * wm + a_row) * 80 + a_kb);
    const uint32_t bofs = (uint32_t)((32 * wn + b_row) * 80 + b_kb);

    float acc[4][4][4];
    #pragma unroll
    for (int i = 0; i < 4; i++)
        #pragma unroll
        for (int j = 0; j < 4; j++)
            #pragma unroll
            for (int q = 0; q < 4; q++) acc[i][j][q] = 0.f;

    auto stageA = [&](uint32_t ub, int ckn) {
        #pragma unroll
        for (int s = 0; s < 2; s++) {
            int t = tid + 256 * s;            // 512 transfers: 128 rows x 4
            int r = t >> 2, pc = t & 3;
            const unsigned short* src = g_Xh
                + (size_t)(imgoff + n0 + r) * CC + ckn * 32 + pc * 8;
            cpasync16(ub + (uint32_t)(r * 80 + pc * 16), src);
        }
    };
    auto stageB = [&](uint32_t ub, int ckn) {
        const char* srcH = (const char*)g_Bimg + (size_t)((ckn * 2 + 0) * 256 + c0) * 80;
        const char* srcL = (const char*)g_Bimg + (size_t)((ckn * 2 + 1) * 256 + c0) * 80;
        #pragma unroll
        for (int s = 0; s < 5; s++) {
            int j = tid + 256 * s;
            if (j < 640) cpasync16(ub + 16 * j, srcH + 16 * j);
            else         cpasync16(ub + 10240 + 16 * (j - 640), srcL + 16 * (j - 640));
        }
    };

    stageA(uA0, 0); stageB(uB0, 0); CP_COMMIT();

    for (int ck = 0; ck < 8; ck++) {
        uint32_t uAc = (ck & 1) ? uA1 : uA0;
        uint32_t uBc = (ck & 1) ? uB1 : uB0;
        if (ck < 7) {
            stageA((ck & 1) ? uA0 : uA1, ck + 1);
            stageB((ck & 1) ? uB0 : uB1, ck + 1);
            CP_COMMIT();
            CP_WAIT1();
        } else {
            CP_WAIT0();
        }
        __syncthreads();

        #pragma unroll
        for (int ks = 0; ks < 2; ks++) {
            uint32_t bh[4][2], bl[4][2];
            #pragma unroll
            for (int nf = 0; nf < 4; nf++) {
                ldm_x2(bh[nf], uBc + bofs + nf * 640 + ks * 32);
                ldm_x2(bl[nf], uBc + 10240 + bofs + nf * 640 + ks * 32);
            }
            #pragma unroll
            for (int mf = 0; mf < 4; mf++) {
                uint32_t ah[4];
                ldm_x4(ah, uAc + aoff + mf * 1280 + ks * 32);
                #pragma unroll
                for (int nf = 0; nf < 4; nf++)
                    mma_f16(acc[mf][nf], ah, bh[nf]);
                #pragma unroll
                for (int nf = 0; nf < 4; nf++)
                    mma_f16(acc[mf][nf], ah, bl[nf]);
            }
        }
        __syncthreads();
    }

    #pragma unroll
    for (int mf = 0; mf < 4; mf++) {
        #pragma unroll
        for (int half = 0; half < 2; half++) {
            int rl = 64 * wm + 16 * mf + (lane >> 2) + 8 * half;
            int grow = n0 + rl;
            if (grow < nrows) {
                float rs = s_rn[rl];
                float* op = O + (size_t)grow * CC + c0 + 32 * wn + 2 * (lane & 3);
                #pragma unroll
                for (int nf = 0; nf < 4; nf++) {
                    float2 v = make_float2(acc[mf][nf][2 * half] * rs,
                                           acc[mf][nf][2 * half + 1] * rs);
                    *(float2*)(op + 8 * nf) = v;
                }
            }
        }
    }
}

// ---------------- kernel: exact per-row top-k (early exit, vectorized) -------
// lane owns classes {4*lane+q, 128+4*lane+q : q in 0..3}
__global__ void topk_k() {
    __shared__ float cs[CC];
    for (int i = threadIdx.x; i < CC; i += blockDim.x) cs[i] = 0.f;
    __syncthreads();
    int warp = threadIdx.x >> 5, lane = threadIdx.x & 31;
    for (int row = blockIdx.x * 8 + warp; row < NU; row += gridDim.x * 8) {
        const float4* pr4 = (const float4*)(g_prob + (size_t)row * CC);
        float4 a0 = pr4[lane], a1 = pr4[lane + 32];
        float v[8] = {a0.x, a0.y, a0.z, a0.w, a1.x, a1.y, a1.z, a1.w};
        unsigned key[8];
        #pragma unroll
        for (int j = 0; j < 8; j++) key[j] = fkey(v[j]);
        unsigned T = 0;
        for (int b = 31; b >= 0; b--) {
            unsigned cand = T | (1u << b);
            int cnt = 0;
            #pragma unroll
            for (int j = 0; j < 8; j++) cnt += (key[j] >= cand);
            cnt = (int)__reduce_add_sync(FULLM, (unsigned)cnt);
            if (cnt >= KTOP) {
                T = cand;
                if (cnt == KTOP) break;   // prefix already selects exactly top-K
            }
        }
        int gt = 0;
        #pragma unroll
        for (int j = 0; j < 8; j++) gt += (key[j] > T);
        gt = (int)__reduce_add_sync(FULLM, (unsigned)gt);
        int r = KTOP - gt;
        int cum = 0;
        unsigned short hq[8];
        #pragma unroll
        for (int j = 0; j < 8; j++) {
            bool eq = (key[j] == T);
            unsigned bal = __ballot_sync(FULLM, eq);
            int pre = cum + __popc(bal & ((1u << lane) - 1u));
            bool keep = (key[j] > T) || (eq && pre < r);
            cum += __popc(bal);
            float o = keep ? v[j] : 0.f;
            hq[j] = __half_as_ushort(__float2half_rn(o));
            if (o != 0.f) {
                int cls = (j < 4) ? (4 * lane + j) : (128 + 4 * lane + (j - 4));
                atomicAdd(&cs[cls], o);
            }
        }
        unsigned short* ph = g_Ph + (size_t)row * CC;
        *(uint2*)(ph + 4 * lane)       = *(uint2*)(hq + 0);
        *(uint2*)(ph + 128 + 4 * lane) = *(uint2*)(hq + 4);
    }
    __syncthreads();
    float c = cs[threadIdx.x];
    if (c != 0.f) atomicAdd(&g_colsum[threadIdx.x], c);
}

// ---------------- split-K fp16 2-product GEMM: S[c][f]+=sum_r p[r][c]x[r][f] -
__global__ void __launch_bounds__(512, 1)
gemm_ptx_mma_k() {
    extern __shared__ char dsm[];
    const uint32_t uS0 = smem_u32(dsm);
    const uint32_t uS1 = uS0 + 34304;

    const int tid = threadIdx.x, lane = tid & 31, wid = tid >> 5;
    const int wm = wid >> 2, wn = wid & 3;
    const int f0 = blockIdx.y * 128;
    const int R0 = blockIdx.x * SEGP;

    auto stage = [&](uint32_t ub, int ck) {
        int r0 = R0 + ck * 32;
        #pragma unroll
        for (int s = 0; s < 4; s++) {
            int t = tid + 512 * s;
            if (t < 1024) {
                int r = t >> 5, piece = t & 31;
                const char* src = (const char*)g_Ph
                                  + (size_t)(r0 + r) * 512 + piece * 16;
                cpasync16(ub + r * 528 + piece * 16, src);
            } else if (t < 1536) {
                int t2 = t - 1024;
                int r = t2 >> 4, piece = t2 & 15;
                const char* src = (const char*)g_Xh
                                  + (size_t)(LL + r0 + r) * 512 + f0 * 2 + piece * 16;
                cpasync16(ub + 16896 + r * 272 + piece * 16, src);
            } else {
                int t2 = t - 1536;
                int r = t2 >> 4, piece = t2 & 15;
                const char* src = (const char*)g_Xl
                                  + (size_t)(LL + r0 + r) * 512 + f0 * 2 + piece * 16;
                cpasync16(ub + 25600 + r * 272 + piece * 16, src);
            }
        }
        CP_COMMIT();
    };

    const int krA = (lane & 7) + 8 * ((lane >> 4) & 1);
    const int cmA = 64 * wm + 8 * ((lane >> 3) & 1);
    const int krB = (lane & 7) + 8 * ((lane >> 3) & 1);
    const uint32_t aoff = (uint32_t)(krA * 528 + 2 * cmA);
    const uint32_t boff = (uint32_t)(krB * 272 + 2 * (32 * wn));

    float acc[4][4][4];
    #pragma unroll
    for (int i = 0; i < 4; i++)
        #pragma unroll
        for (int j = 0; j < 4; j++)
            #pragma unroll
            for (int q = 0; q < 4; q++) acc[i][j][q] = 0.f;

    stage(uS0, 0);

    for (int ck = 0; ck < CHKP; ck++) {
        if (ck + 1 < CHKP) {
            stage((ck & 1) ? uS0 : uS1, ck + 1);
            CP_WAIT1();
        } else {
            CP_WAIT0();
        }
        __syncthreads();

        uint32_t uP = (ck & 1) ? uS1 : uS0;
        uint32_t uXh = uP + 16896;
        uint32_t uXl = uP + 25600;
        #pragma unroll
        for (int ks = 0; ks < 2; ks++) {
            uint32_t bh[4][2], bl[4][2];
            #pragma unroll
            for (int nf = 0; nf < 4; nf++) {
                uint32_t bo = (uint32_t)(ks * 16 * 272) + boff + 2 * (8 * nf);
                ldmT_x2(bh[nf], uXh + bo);
                ldmT_x2(bl[nf], uXl + bo);
            }
            #pragma unroll
            for (int mf = 0; mf < 4; mf++) {
                uint32_t aa = uP + (uint32_t)(ks * 16 * 528) + aoff + 2 * (16 * mf);
                uint32_t ah[4];
                ldmT_x4(ah, aa);
                #pragma unroll
                for (int nf = 0; nf < 4; nf++)
                    mma_f16(acc[mf][nf], ah, bh[nf]);
                #pragma unroll
                for (int nf = 0; nf < 4; nf++)
                    mma_f16(acc[mf][nf], ah, bl[nf]);
            }
        }
        __syncthreads();
    }

    #pragma unroll
    for (int mf = 0; mf < 4; mf++) {
        #pragma unroll
        for (int nf = 0; nf < 4; nf++) {
            #pragma unroll
            for (int half = 0; half < 2; half++) {
                int c = 64 * wm + 16 * mf + (lane >> 2) + 8 * half;
                int f = f0 + 32 * wn + 8 * nf + 2 * (lane & 3);
                atomicAdd(&g_S[c * CC + f + 0], acc[mf][nf][2 * half + 0]);
                atomicAdd(&g_S[c * CC + f + 1], acc[mf][nf][2 * half + 1]);
            }
        }
    }
}

// ---------------- kernel: proto update + renorm + split write ----------------
__global__ void pfin2_k() {
    int c = blockIdx.x, f = threadIdx.x;
    float cp = g_colsum[c];
    float denom = cp + (float)g_cntlab[c];
    float pv = g_protos[c * CC + f];
    float nv = pv + g_S[c * CC + f] / denom - (cp / denom) * pv;
    float tot = block_reduce_sum(nv * nv);
    write_bimg(c, f, nv * rsqrtf(fmaxf(tot, 1e-12f)));
}

// ---------------- launch ------------------------------------------------------
extern "C" void kernel_launch(void* const* d_in, const int* in_sizes, int n_in,
                              void* d_out, int out_size) {
    (void)in_sizes; (void)n_in; (void)out_size;
    const float* x = (const float*)d_in[0];
    const float* labels = (const float*)d_in[1];
    float* out = (float*)d_out;

    cudaFuncSetAttribute(gemm_mma_k,
                         cudaFuncAttributeMaxDynamicSharedMemorySize, SMEM_MMA);
    cudaFuncSetAttribute(gemm_ptx_mma_k,
                         cudaFuncAttributeMaxDynamicSharedMemorySize, SMEM_PTX);

    zero_k<<<CC, 256>>>();                                    // 1
    prep_k<<<1480, 256>>>(x, labels);                         // 2 (+psum fused)
    pfin_k<<<CC, 256>>>();                                    // 3
    gemm_mma_k<<<dim3((NU + 127) / 128, 2), 256, SMEM_MMA>>>( // 4 <- ncu capture
        nullptr, LL, NU);
    topk_k<<<1563, 256>>>();                                  // 5
    gemm_ptx_mma_k<<<dim3(NSEGP, 2), 512, SMEM_PTX>>>();      // 6
    pfin2_k<<<CC, 256>>>();                                   // 7
    gemm_mma_k<<<dim3((NN + 127) / 128, 2), 256, SMEM_MMA>>>(out, 0, NN); // 8
}

// round 14
// speedup vs baseline: 1.5483x; 1.0115x over previous
#include <cuda_runtime.h>
#include <cuda_fp16.h>
#include <cstdint>

#define FULLM 0xffffffffu
#define DINLINE __device__ __forceinline__

constexpr int NN = 150000, CC = 256, LL = 50000, KTOP = 200;
constexpr int NU = NN - LL;
constexpr int SEGP = 1376;             // 43 chunks of 32 rows
constexpr int NSEGP = 73;              // 73 * 1376 = 100448 >= NU
constexpr int CHKP = 43;
constexpr int NPAD = NSEGP * SEGP;     // padded unlabeled rows
constexpr int NIMG = LL + NPAD;        // 150448 image rows (>= NN, pad zero)
// xpt smem: A-hi double (2*10240) + B h+l double (2*20480) = 61440
constexpr int SMEM_MMA = 61440;
// ptx smem per stage: ph 16896 + xh 8704 + xl 8704 = 34304, x2 = 68608
constexpr int SMEM_PTX = 68608;

// ---------------- scratch (device globals; no allocation allowed) ------------
__device__ __align__(16) unsigned short g_prob16[(size_t)NU * CC];  // fp16 prob
__device__ float g_rnorm[NN];
__device__ float g_psum[CC * CC];
__device__ float g_protos[CC * CC];
__device__ float g_S[CC * CC];
__device__ float g_colsum[CC];
__device__ int   g_cntall[CC];
__device__ int   g_cntlab[CC];
// protoN as fp16 hi/lo smem-image: [chunk 8][hl 2][class 256][40 shorts (80B pitch)]
__device__ __align__(16) unsigned short g_Bimg[8 * 2 * 256 * 40];
// masked-p fp16 image [NPAD][256] (pad rows stay zero)
__device__ __align__(16) unsigned short g_Ph[(size_t)NPAD * CC];
// raw-x fp16 hi/lo images, GLOBAL row index [NIMG][256] (pad rows zero)
__device__ __align__(16) unsigned short g_Xh[(size_t)NIMG * CC];
__device__ __align__(16) unsigned short g_Xl[(size_t)NIMG * CC];

// ---------------- helpers ----------------------------------------------------
DINLINE float block_reduce_sum(float v) {
    __shared__ float red[8];
    __shared__ float tot;
    for (int o = 16; o; o >>= 1) v += __shfl_xor_sync(FULLM, v, o);
    if ((threadIdx.x & 31) == 0) red[threadIdx.x >> 5] = v;
    __syncthreads();
    if (threadIdx.x < 32) {
        float s = (threadIdx.x < 8) ? red[threadIdx.x] : 0.f;
        for (int o = 4; o; o >>= 1) s += __shfl_xor_sync(FULLM, s, o);
        if (threadIdx.x == 0) tot = s;
    }
    __syncthreads();
    return tot;
}
DINLINE uint32_t smem_u32(const void* p) {
    uint32_t a;
    asm("{ .reg .u64 t; cvta.to.shared.u64 t, %1; cvt.u32.u64 %0, t; }"
        : "=r"(a) : "l"(p));
    return a;
}
// fp16 split: h = fp16(v), l = fp16(v - h)
DINLINE void hsplit(float v, unsigned short& h, unsigned short& l) {
    __half hh = __float2half_rn(v);
    float hf = __half2float(hh);
    __half ll = __float2half_rn(v - hf);
    h = __half_as_ushort(hh);
    l = __half_as_ushort(ll);
}
DINLINE void cpasync16(uint32_t dst, const void* src) {
    asm volatile("cp.async.ca.shared.global [%0], [%1], 16;"
                 :: "r"(dst), "l"(src));
}
#define CP_COMMIT() asm volatile("cp.async.commit_group;" ::: "memory")
#define CP_WAIT0()  asm volatile("cp.async.wait_group 0;" ::: "memory")
#define CP_WAIT1()  asm volatile("cp.async.wait_group 1;" ::: "memory")

DINLINE void ldm_x4(uint32_t* r, uint32_t addr) {
    asm volatile("ldmatrix.sync.aligned.m8n8.x4.shared.b16 {%0,%1,%2,%3}, [%4];"
                 : "=r"(r[0]), "=r"(r[1]), "=r"(r[2]), "=r"(r[3]) : "r"(addr));
}
DINLINE void ldm_x2(uint32_t* r, uint32_t addr) {
    asm volatile("ldmatrix.sync.aligned.m8n8.x2.shared.b16 {%0,%1}, [%2];"
                 : "=r"(r[0]), "=r"(r[1]) : "r"(addr));
}
DINLINE void ldmT_x4(uint32_t* r, uint32_t addr) {
    asm volatile("ldmatrix.sync.aligned.m8n8.x4.trans.shared.b16 {%0,%1,%2,%3}, [%4];"
                 : "=r"(r[0]), "=r"(r[1]), "=r"(r[2]), "=r"(r[3]) : "r"(addr));
}
DINLINE void ldmT_x2(uint32_t* r, uint32_t addr) {
    asm volatile("ldmatrix.sync.aligned.m8n8.x2.trans.shared.b16 {%0,%1}, [%2];"
                 : "=r"(r[0]), "=r"(r[1]) : "r"(addr));
}
DINLINE void mma_f16(float* c, const uint32_t* a, const uint32_t* b) {
    asm volatile(
        "mma.sync.aligned.m16n8k16.row.col.f32.f16.f16.f32 "
        "{%0,%1,%2,%3}, {%4,%5,%6,%7}, {%8,%9}, {%0,%1,%2,%3};"
        : "+f"(c[0]), "+f"(c[1]), "+f"(c[2]), "+f"(c[3])
        : "r"(a[0]), "r"(a[1]), "r"(a[2]), "r"(a[3]), "r"(b[0]), "r"(b[1]));
}

// ---------------- kernel 0: zero accumulators --------------------------------
__global__ void zero_k() {
    int i = blockIdx.x * blockDim.x + threadIdx.x;
    if (i < CC * CC) { g_psum[i] = 0.f; g_S[i] = 0.f; }
    if (i < CC) { g_colsum[i] = 0.f; g_cntall[i] = 0; g_cntlab[i] = 0; }
}

// ---------------- kernel 1: cls, rnorm, hist, psum atomics, x fp16 image -----
__global__ void prep_k(const float* __restrict__ x, const float* __restrict__ labels) {
    __shared__ int s_all[CC], s_lab[CC];
    for (int i = threadIdx.x; i < CC; i += blockDim.x) { s_all[i] = 0; s_lab[i] = 0; }
    __syncthreads();
    int warp = threadIdx.x >> 5, lane = threadIdx.x & 31;
    int wpb = blockDim.x >> 5;
    for (int row = blockIdx.x * wpb + warp; row < NN; row += gridDim.x * wpb) {
        const float4* lr4 = (const float4*)(labels + (size_t)row * CC);
        int myc = -1;
        #pragma unroll
        for (int j = 0; j < 2; j++) {
            float4 lv = lr4[lane + 32 * j];
            int cb = 4 * (lane + 32 * j);
            if (lv.x > 0.5f) myc = cb + 0;
            if (lv.y > 0.5f) myc = cb + 1;
            if (lv.z > 0.5f) myc = cb + 2;
            if (lv.w > 0.5f) myc = cb + 3;
        }
        int cls = __reduce_max_sync(FULLM, myc);
        const float4* xr = (const float4*)(x + (size_t)row * CC);
        float ss = 0.f;
        float4 v[2];
        #pragma unroll
        for (int j = 0; j < 2; j++) {
            v[j] = xr[lane + 32 * j];
            ss += v[j].x * v[j].x + v[j].y * v[j].y + v[j].z * v[j].z + v[j].w * v[j].w;
        }
        for (int o = 16; o; o >>= 1) ss += __shfl_xor_sync(FULLM, ss, o);
        if (lane == 0) {
            g_rnorm[row] = rsqrtf(fmaxf(ss, 1e-12f));
            atomicAdd(&s_all[cls], 1);
            if (row < LL) atomicAdd(&s_lab[cls], 1);
        }
        if (row < LL) {   // fused per-class labeled feature sums
            float* ps = g_psum + cls * CC;
            #pragma unroll
            for (int j = 0; j < 2; j++) {
                int fb = 4 * (lane + 32 * j);
                atomicAdd(ps + fb + 0, v[j].x);
                atomicAdd(ps + fb + 1, v[j].y);
                atomicAdd(ps + fb + 2, v[j].z);
                atomicAdd(ps + fb + 3, v[j].w);
            }
        }
        // fp16 split image: hi for all rows; lo only for unlabeled (sole consumer)
        size_t ur = (size_t)row * CC;
        bool needL = row >= LL;
        #pragma unroll
        for (int j = 0; j < 2; j++) {
            int fb = 4 * (lane + 32 * j);
            unsigned short h[4], l[4];
            hsplit(v[j].x, h[0], l[0]);
            hsplit(v[j].y, h[1], l[1]);
            hsplit(v[j].z, h[2], l[2]);
            hsplit(v[j].w, h[3], l[3]);
            *(uint2*)(g_Xh + ur + fb) = *(uint2*)h;
            if (needL) *(uint2*)(g_Xl + ur + fb) = *(uint2*)l;
        }
    }
    __syncthreads();
    for (int i = threadIdx.x; i < CC; i += blockDim.x) {
        if (s_all[i]) atomicAdd(&g_cntall[i], s_all[i]);
        if (s_lab[i]) atomicAdd(&g_cntlab[i], s_lab[i]);
    }
}

// ---------------- write protoN split (fp16 hi/lo) into image -----------------
DINLINE void write_bimg(int c, int f, float v) {
    unsigned short h, l;
    hsplit(v, h, l);
    int ck = f >> 5, kl = f & 31;
    g_Bimg[((ck * 2 + 0) * 256 + c) * 40 + kl] = h;
    g_Bimg[((ck * 2 + 1) * 256 + c) * 40 + kl] = l;
}

// ---------------- kernel: protos + normalized protoN split -------------------
__global__ void pfin_k() {
    int c = blockIdx.x, f = threadIdx.x;
    float v = g_psum[c * CC + f] / (float)g_cntall[c];
    g_protos[c * CC + f] = v;
    float tot = block_reduce_sum(v * v);
    write_bimg(c, f, v * rsqrtf(fmaxf(tot, 1e-12f)));
}

// ---------------- fp16 2-product mma GEMM: OUT[n][c]=rnorm[n]*(X[n].pN[c]) ---
// block 128 rows x 128 classes (grid.y=2), 8 warps, warp tile 64x32, 2 CTA/SM.
// D = Ah*Bh + Ah*Bl. H16: store fp16 into g_prob16; else fp32 into OUT.
template <bool H16>
__global__ void __launch_bounds__(256, 2)
gemm_mma_k(float* __restrict__ OUT, int imgoff, int nrows) {
    extern __shared__ char dsm[];
    __shared__ float s_rn[128];

    const int tid = threadIdx.x, lane = tid & 31, wid = tid >> 5;
    const int wm = wid >> 2, wn = wid & 3;
    const int n0 = blockIdx.x * 128;
    const int c0 = blockIdx.y * 128;

    const uint32_t uA0 = smem_u32(dsm);
    const uint32_t uA1 = uA0 + 10240;
    const uint32_t uB0 = uA0 + 20480;
    const uint32_t uB1 = uA0 + 40960;

    if (tid < 128) {
        int r = n0 + tid;
        s_rn[tid] = (r < nrows) ? g_rnorm[imgoff + r] : 0.f;
    }

    const int a_row = (lane & 7) + 8 * ((lane >> 3) & 1);
    const int a_kb  = 16 * (lane >> 4);
    const int b_row = lane & 7;
    const int b_kb  = 16 * ((lane >> 3) & 1);
    const uint32_t aoff = (uint32_t)((64 * wm + a_row) * 80 + a_kb);
    const uint32_t bofs = (uint32_t)((32 * wn + b_row) * 80 + b_kb);

    float acc[4][4][4];
    #pragma unroll
    for (int i = 0; i < 4; i++)
        #pragma unroll
        for (int j = 0; j < 4; j++)
            #pragma unroll
            for (int q = 0; q < 4; q++) acc[i][j][q] = 0.f;

    auto stageA = [&](uint32_t ub, int ckn) {
        #pragma unroll
        for (int s = 0; s < 2; s++) {
            int t = tid + 256 * s;            // 512 transfers: 128 rows x 4
            int r = t >> 2, pc = t & 3;
            const unsigned short* src = g_Xh
                + (size_t)(imgoff + n0 + r) * CC + ckn * 32 + pc * 8;
            cpasync16(ub + (uint32_t)(r * 80 + pc * 16), src);
        }
    };
    auto stageB = [&](uint32_t ub, int ckn) {
        const char* srcH = (const char*)g_Bimg + (size_t)((ckn * 2 + 0) * 256 + c0) * 80;
        const char* srcL = (const char*)g_Bimg + (size_t)((ckn * 2 + 1) * 256 + c0) * 80;
        #pragma unroll
        for (int s = 0; s < 5; s++) {
            int j = tid + 256 * s;
            if (j < 640) cpasync16(ub + 16 * j, srcH + 16 * j);
            else         cpasync16(ub + 10240 + 16 * (j - 640), srcL + 16 * (j - 640));
        }
    };

    stageA(uA0, 0); stageB(uB0, 0); CP_COMMIT();

    for (int ck = 0; ck < 8; ck++) {
        uint32_t uAc = (ck & 1) ? uA1 : uA0;
        uint32_t uBc = (ck & 1) ? uB1 : uB0;
        if (ck < 7) {
            stageA((ck & 1) ? uA0 : uA1, ck + 1);
            stageB((ck & 1) ? uB0 : uB1, ck + 1);
            CP_COMMIT();
            CP_WAIT1();
        } else {
            CP_WAIT0();
        }
        __syncthreads();

        #pragma unroll
        for (int ks = 0; ks < 2; ks++) {
            uint32_t bh[4][2], bl[4][2];
            #pragma unroll
            for (int nf = 0; nf < 4; nf++) {
                ldm_x2(bh[nf], uBc + bofs + nf * 640 + ks * 32);
                ldm_x2(bl[nf], uBc + 10240 + bofs + nf * 640 + ks * 32);
            }
            #pragma unroll
            for (int mf = 0; mf < 4; mf++) {
                uint32_t ah[4];
                ldm_x4(ah, uAc + aoff + mf * 1280 + ks * 32);
                #pragma unroll
                for (int nf = 0; nf < 4; nf++)
                    mma_f16(acc[mf][nf], ah, bh[nf]);
                #pragma unroll
                for (int nf = 0; nf < 4; nf++)
                    mma_f16(acc[mf][nf], ah, bl[nf]);
            }
        }
        __syncthreads();
    }

    #pragma unroll
    for (int mf = 0; mf < 4; mf++) {
        #pragma unroll
        for (int half = 0; half < 2; half++) {
            int rl = 64 * wm + 16 * mf + (lane >> 2) + 8 * half;
            int grow = n0 + rl;
            if (grow < nrows) {
                float rs = s_rn[rl];
                if constexpr (H16) {
                    unsigned short* op = g_prob16 + (size_t)grow * CC
                                         + c0 + 32 * wn + 2 * (lane & 3);
                    #pragma unroll
                    for (int nf = 0; nf < 4; nf++) {
                        __half2 hv = __floats2half2_rn(acc[mf][nf][2 * half] * rs,
                                                       acc[mf][nf][2 * half + 1] * rs);
                        *(__half2*)(op + 8 * nf) = hv;
                    }
                } else {
                    float* op = OUT + (size_t)grow * CC + c0 + 32 * wn + 2 * (lane & 3);
                    #pragma unroll
                    for (int nf = 0; nf < 4; nf++) {
                        float2 v = make_float2(acc[mf][nf][2 * half] * rs,
                                               acc[mf][nf][2 * half + 1] * rs);
                        *(float2*)(op + 8 * nf) = v;
                    }
                }
            }
        }
    }
}

// ---------------- kernel: exact per-row top-k on fp16 keys -> Ph + colsum ----
// lane owns classes {4*lane+q, 128+4*lane+q : q in 0..3}; 16-bit radix, early exit
__global__ void topk_k() {
    __shared__ float cs[CC];
    for (int i = threadIdx.x; i < CC; i += blockDim.x) cs[i] = 0.f;
    __syncthreads();
    int warp = threadIdx.x >> 5, lane = threadIdx.x & 31;
    for (int row = blockIdx.x * 8 + warp; row < NU; row += gridDim.x * 8) {
        const unsigned short* pr = g_prob16 + (size_t)row * CC;
        uint2 q0 = *(const uint2*)(pr + 4 * lane);
        uint2 q1 = *(const uint2*)(pr + 128 + 4 * lane);
        unsigned short hv[8] = {
            (unsigned short)(q0.x & 0xffff), (unsigned short)(q0.x >> 16),
            (unsigned short)(q0.y & 0xffff), (unsigned short)(q0.y >> 16),
            (unsigned short)(q1.x & 0xffff), (unsigned short)(q1.x >> 16),
            (unsigned short)(q1.y & 0xffff), (unsigned short)(q1.y >> 16) };
        unsigned key[8];
        #pragma unroll
        for (int j = 0; j < 8; j++) {
            unsigned s = hv[j];
            key[j] = (s & 0x8000u) ? (~s & 0xFFFFu) : (s | 0x8000u);
        }
        unsigned T = 0;
        for (int b = 15; b >= 0; b--) {
            unsigned cand = T | (1u << b);
            int cnt = 0;
            #pragma unroll
            for (int j = 0; j < 8; j++) cnt += (key[j] >= cand);
            cnt = (int)__reduce_add_sync(FULLM, (unsigned)cnt);
            if (cnt >= KTOP) {
                T = cand;
                if (cnt == KTOP) break;   // prefix already selects exactly top-K
            }
        }
        int gt = 0;
        #pragma unroll
        for (int j = 0; j < 8; j++) gt += (key[j] > T);
        gt = (int)__reduce_add_sync(FULLM, (unsigned)gt);
        int r = KTOP - gt;
        int cum = 0;
        unsigned short hq[8];
        #pragma unroll
        for (int j = 0; j < 8; j++) {
            bool eq = (key[j] == T);
            unsigned bal = __ballot_sync(FULLM, eq);
            int pre = cum + __popc(bal & ((1u << lane) - 1u));
            bool keep = (key[j] > T) || (eq && pre < r);
            cum += __popc(bal);
            hq[j] = keep ? hv[j] : (unsigned short)0;
            if (keep) {
                float o = __half2float(__ushort_as_half(hv[j]));
                if (o != 0.f) {
                    int cls = (j < 4) ? (4 * lane + j) : (128 + 4 * lane + (j - 4));
                    atomicAdd(&cs[cls], o);
                }
            }
        }
        unsigned short* ph = g_Ph + (size_t)row * CC;
        *(uint2*)(ph + 4 * lane)       = *(uint2*)(hq + 0);
        *(uint2*)(ph + 128 + 4 * lane) = *(uint2*)(hq + 4);
    }
    __syncthreads();
    float c = cs[threadIdx.x];
    if (c != 0.f) atomicAdd(&g_colsum[threadIdx.x], c);
}

// ---------------- split-K fp16 2-product GEMM: S[c][f]+=sum_r p[r][c]x[r][f] -
__global__ void __launch_bounds__(512, 1)
gemm_ptx_mma_k() {
    extern __shared__ char dsm[];
    const uint32_t uS0 = smem_u32(dsm);
    const uint32_t uS1 = uS0 + 34304;

    const int tid = threadIdx.x, lane = tid & 31, wid = tid >> 5;
    const int wm = wid >> 2, wn = wid & 3;
    const int f0 = blockIdx.y * 128;
    const int R0 = blockIdx.x * SEGP;

    auto stage = [&](uint32_t ub, int ck) {
        int r0 = R0 + ck * 32;
        #pragma unroll
        for (int s = 0; s < 4; s++) {
            int t = tid + 512 * s;
            if (t < 1024) {
                int r = t >> 5, piece = t & 31;
                const char* src = (const char*)g_Ph
                                  + (size_t)(r0 + r) * 512 + piece * 16;
                cpasync16(ub + r * 528 + piece * 16, src);
            } else if (t < 1536) {
                int t2 = t - 1024;
                int r = t2 >> 4, piece = t2 & 15;
                const char* src = (const char*)g_Xh
                                  + (size_t)(LL + r0 + r) * 512 + f0 * 2 + piece * 16;
                cpasync16(ub + 16896 + r * 272 + piece * 16, src);
            } else {
                int t2 = t - 1536;
                int r = t2 >> 4, piece = t2 & 15;
                const char* src = (const char*)g_Xl
                                  + (size_t)(LL + r0 + r) * 512 + f0 * 2 + piece * 16;
                cpasync16(ub + 25600 + r * 272 + piece * 16, src);
            }
        }
        CP_COMMIT();
    };

    const int krA = (lane & 7) + 8 * ((lane >> 4) & 1);
    const int cmA = 64 * wm + 8 * ((lane >> 3) & 1);
    const int krB = (lane & 7) + 8 * ((lane >> 3) & 1);
    const uint32_t aoff = (uint32_t)(krA * 528 + 2 * cmA);
    const uint32_t boff = (uint32_t)(krB * 272 + 2 * (32 * wn));

    float acc[4][4][4];
    #pragma unroll
    for (int i = 0; i < 4; i++)
        #pragma unroll
        for (int j = 0; j < 4; j++)
            #pragma unroll
            for (int q = 0; q < 4; q++) acc[i][j][q] = 0.f;

    stage(uS0, 0);

    for (int ck = 0; ck < CHKP; ck++) {
        if (ck + 1 < CHKP) {
            stage((ck & 1) ? uS0 : uS1, ck + 1);
            CP_WAIT1();
        } else {
            CP_WAIT0();
        }
        __syncthreads();

        uint32_t uP = (ck & 1) ? uS1 : uS0;
        uint32_t uXh = uP + 16896;
        uint32_t uXl = uP + 25600;
        #pragma unroll
        for (int ks = 0; ks < 2; ks++) {
            uint32_t bh[4][2], bl[4][2];
            #pragma unroll
            for (int nf = 0; nf < 4; nf++) {
                uint32_t bo = (uint32_t)(ks * 16 * 272) + boff + 2 * (8 * nf);
                ldmT_x2(bh[nf], uXh + bo);
                ldmT_x2(bl[nf], uXl + bo);
            }
            #pragma unroll
            for (int mf = 0; mf < 4; mf++) {
                uint32_t aa = uP + (uint32_t)(ks * 16 * 528) + aoff + 2 * (16 * mf);
                uint32_t ah[4];
                ldmT_x4(ah, aa);
                #pragma unroll
                for (int nf = 0; nf < 4; nf++)
                    mma_f16(acc[mf][nf], ah, bh[nf]);
                #pragma unroll
                for (int nf = 0; nf < 4; nf++)
                    mma_f16(acc[mf][nf], ah, bl[nf]);
            }
        }
        __syncthreads();
    }

    #pragma unroll
    for (int mf = 0; mf < 4; mf++) {
        #pragma unroll
        for (int nf = 0; nf < 4; nf++) {
            #pragma unroll
            for (int half = 0; half < 2; half++) {
                int c = 64 * wm + 16 * mf + (lane >> 2) + 8 * half;
                int f = f0 + 32 * wn + 8 * nf + 2 * (lane & 3);
                atomicAdd(&g_S[c * CC + f + 0], acc[mf][nf][2 * half + 0]);
                atomicAdd(&g_S[c * CC + f + 1], acc[mf][nf][2 * half + 1]);
            }
        }
    }
}

// ---------------- kernel: proto update + renorm + split write ----------------
__global__ void pfin2_k() {
    int c = blockIdx.x, f = threadIdx.x;
    float cp = g_colsum[c];
    float denom = cp + (float)g_cntlab[c];
    float pv = g_protos[c * CC + f];
    float nv = pv + g_S[c * CC + f] / denom - (cp / denom) * pv;
    float tot = block_reduce_sum(nv * nv);
    write_bimg(c, f, nv * rsqrtf(fmaxf(tot, 1e-12f)));
}

// ---------------- launch ------------------------------------------------------
extern "C" void kernel_launch(void* const* d_in, const int* in_sizes, int n_in,
                              void* d_out, int out_size) {
    (void)in_sizes; (void)n_in; (void)out_size;
    const float* x = (const float*)d_in[0];
    const float* labels = (const float*)d_in[1];
    float* out = (float*)d_out;

    cudaFuncSetAttribute(gemm_mma_k<true>,
                         cudaFuncAttributeMaxDynamicSharedMemorySize, SMEM_MMA);
    cudaFuncSetAttribute(gemm_mma_k<false>,
                         cudaFuncAttributeMaxDynamicSharedMemorySize, SMEM_MMA);
    cudaFuncSetAttribute(gemm_ptx_mma_k,
                         cudaFuncAttributeMaxDynamicSharedMemorySize, SMEM_PTX);

    zero_k<<<CC, 256>>>();                                    // 1
    prep_k<<<1480, 256>>>(x, labels);                         // 2
    pfin_k<<<CC, 256>>>();                                    // 3
    gemm_mma_k<true><<<dim3((NU + 127) / 128, 2), 256, SMEM_MMA>>>( // 4 (prob fp16)
        nullptr, LL, NU);
    topk_k<<<1563, 256>>>();                                  // 5
    gemm_ptx_mma_k<<<dim3(NSEGP, 2), 512, SMEM_PTX>>>();      // 6
    pfin2_k<<<CC, 256>>>();                                   // 7
    gemm_mma_k<false><<<dim3((NN + 127) / 128, 2), 256, SMEM_MMA>>>(out, 0, NN); // 8
}